// round 6
// baseline (speedup 1.0000x reference)
#include <cuda_runtime.h>
#include <mma.h>
#include <math.h>

using namespace nvcuda;

// BERT-base forward: B=4, S=512, L=12, D=768, H=12, F=3072, V=30522
#define Bq 4
#define Sq 512
#define Lq 12
#define Dq 768
#define Hq 12
#define Fq 3072
#define Vq 30522
#define HDq 64
#define Tq 2048   // B*S tokens

// Workspace: x,q,k,v,t,x1 [T,D] + h [T,F]  = 60 MB
__device__ float g_ws[6 * (size_t)Tq * Dq + (size_t)Tq * Fq];

__device__ __forceinline__ float T32(float x) { return wmma::__float_to_tf32(x); }

// ---------------------------------------------------------------------------
// Block-wide sum of (a,b) pairs, 256 threads
// ---------------------------------------------------------------------------
__device__ __forceinline__ float2 blockReduce2(float a, float b) {
#pragma unroll
    for (int o = 16; o > 0; o >>= 1) {
        a += __shfl_down_sync(0xffffffffu, a, o);
        b += __shfl_down_sync(0xffffffffu, b, o);
    }
    __shared__ float2 sh[8];
    int lane = threadIdx.x & 31, wid = threadIdx.x >> 5;
    if (lane == 0) sh[wid] = make_float2(a, b);
    __syncthreads();
    if (wid == 0) {
        float2 v = (lane < 8) ? sh[lane] : make_float2(0.f, 0.f);
#pragma unroll
        for (int o = 4; o > 0; o >>= 1) {
            v.x += __shfl_down_sync(0xffffffffu, v.x, o);
            v.y += __shfl_down_sync(0xffffffffu, v.y, o);
        }
        if (lane == 0) sh[0] = v;
    }
    __syncthreads();
    return sh[0];
}

// ---------------------------------------------------------------------------
// Embedding + LayerNorm: one block per token, 256 threads (3 elems each)
// ---------------------------------------------------------------------------
__global__ void embed_ln_kernel(const int* __restrict__ ids,
                                const float* __restrict__ wemb,
                                const float* __restrict__ pemb,
                                const float* __restrict__ semb,
                                const float* __restrict__ g,
                                const float* __restrict__ bta,
                                float* __restrict__ x) {
    int t = blockIdx.x;
    int s = t & (Sq - 1);
    int id = ids[t];
    float v[3];
    float sum = 0.f, sq = 0.f;
#pragma unroll
    for (int i = 0; i < 3; i++) {
        int d = threadIdx.x + i * 256;
        float val = wemb[(size_t)id * Dq + d] + pemb[(size_t)s * Dq + d] + semb[d];
        v[i] = val;
        sum += val;
        sq += val * val;
    }
    float2 r = blockReduce2(sum, sq);
    float mu = r.x * (1.0f / Dq);
    float var = r.y * (1.0f / Dq) - mu * mu;
    float rstd = rsqrtf(var + 1e-5f);
#pragma unroll
    for (int i = 0; i < 3; i++) {
        int d = threadIdx.x + i * 256;
        x[(size_t)t * Dq + d] = (v[i] - mu) * rstd * g[d] + bta[d];
    }
}

// ---------------------------------------------------------------------------
// out = LayerNorm(a + bvec) * g + beta : one block per token
// ---------------------------------------------------------------------------
__global__ void add_ln_kernel(const float* __restrict__ a,
                              const float* __restrict__ bvec,
                              const float* __restrict__ g,
                              const float* __restrict__ bta,
                              float* __restrict__ out) {
    int t = blockIdx.x;
    float v[3];
    float sum = 0.f, sq = 0.f;
#pragma unroll
    for (int i = 0; i < 3; i++) {
        int d = threadIdx.x + i * 256;
        float val = a[(size_t)t * Dq + d] + bvec[(size_t)t * Dq + d];
        v[i] = val;
        sum += val;
        sq += val * val;
    }
    float2 r = blockReduce2(sum, sq);
    float mu = r.x * (1.0f / Dq);
    float var = r.y * (1.0f / Dq) - mu * mu;
    float rstd = rsqrtf(var + 1e-5f);
#pragma unroll
    for (int i = 0; i < 3; i++) {
        int d = threadIdx.x + i * 256;
        out[(size_t)t * Dq + d] = (v[i] - mu) * rstd * g[d] + bta[d];
    }
}

// ---------------------------------------------------------------------------
// TF32 WMMA GEMM body: C[M,N] = A[M,K] @ B[K,N], row-major.
// 128x128 block tile, BK=32, 8 warps (4 in M x 2 in N), warp tile 32x64.
// EPI: 0=none, 1=+bias, 2=+bias then exact GELU. M%128==0, K%32==0, N any.
// ALIGN4: B rows are 16B-aligned (N % 4 == 0) -> float4 loads.
//         otherwise N must be even -> float2 loads (8B-aligned rows).
// ---------------------------------------------------------------------------
template <int EPI, bool ALIGN4>
__device__ __forceinline__ void gemm_body(const float* __restrict__ A,
                                          const float* __restrict__ Bm,
                                          const float* __restrict__ bias,
                                          float* __restrict__ C,
                                          int M, int N, int K) {
    __shared__ float As[128][36];
    __shared__ float Bs[32][132];
    __shared__ float Cs[8][16][20];

    int tid = threadIdx.x;
    int row0 = blockIdx.y * 128, col0 = blockIdx.x * 128;
    int warp = tid >> 5, lane = tid & 31;
    int wm = warp & 3, wn = warp >> 2;

    wmma::fragment<wmma::accumulator, 16, 16, 8, float> acc[2][4];
#pragma unroll
    for (int i = 0; i < 2; i++)
#pragma unroll
        for (int j = 0; j < 4; j++)
            wmma::fill_fragment(acc[i][j], 0.0f);

    int aRow = tid >> 3;
    int aCol = (tid & 7) * 4;
    int bRowBase = tid >> 5;
    int bCol = (tid & 31) * 4;

    for (int k0 = 0; k0 < K; k0 += 32) {
#pragma unroll
        for (int it = 0; it < 4; it++) {
            int r = aRow + it * 32;
            float4 v = *(const float4*)(A + (size_t)(row0 + r) * K + k0 + aCol);
            As[r][aCol + 0] = T32(v.x);
            As[r][aCol + 1] = T32(v.y);
            As[r][aCol + 2] = T32(v.z);
            As[r][aCol + 3] = T32(v.w);
        }
#pragma unroll
        for (int it = 0; it < 4; it++) {
            int r = bRowBase + it * 8;
            const float* p = Bm + (size_t)(k0 + r) * N + col0 + bCol;
            if (ALIGN4) {
                float4 v = *(const float4*)p;
                Bs[r][bCol + 0] = T32(v.x);
                Bs[r][bCol + 1] = T32(v.y);
                Bs[r][bCol + 2] = T32(v.z);
                Bs[r][bCol + 3] = T32(v.w);
            } else {
                int c = col0 + bCol;
                if (c + 3 < N) {
                    // rows are 8B-aligned (N even), col multiple of 4 -> float2 ok
                    float2 v0 = *(const float2*)p;
                    float2 v1 = *(const float2*)(p + 2);
                    Bs[r][bCol + 0] = T32(v0.x);
                    Bs[r][bCol + 1] = T32(v0.y);
                    Bs[r][bCol + 2] = T32(v1.x);
                    Bs[r][bCol + 3] = T32(v1.y);
                } else {
#pragma unroll
                    for (int e = 0; e < 4; e++)
                        Bs[r][bCol + e] = (c + e < N) ? T32(p[e]) : 0.f;
                }
            }
        }
        __syncthreads();

#pragma unroll
        for (int kk = 0; kk < 4; kk++) {
            wmma::fragment<wmma::matrix_a, 16, 16, 8, wmma::precision::tf32, wmma::row_major> af[2];
            wmma::fragment<wmma::matrix_b, 16, 16, 8, wmma::precision::tf32, wmma::row_major> bf[4];
#pragma unroll
            for (int i = 0; i < 2; i++)
                wmma::load_matrix_sync(af[i], &As[wm * 32 + i * 16][kk * 8], 36);
#pragma unroll
            for (int j = 0; j < 4; j++)
                wmma::load_matrix_sync(bf[j], &Bs[kk * 8][wn * 64 + j * 16], 132);
#pragma unroll
            for (int i = 0; i < 2; i++)
#pragma unroll
                for (int j = 0; j < 4; j++)
                    wmma::mma_sync(acc[i][j], af[i], bf[j], acc[i][j]);
        }
        __syncthreads();
    }

    int rr = lane >> 1, cc = (lane & 1) * 8;
#pragma unroll
    for (int i = 0; i < 2; i++) {
#pragma unroll
        for (int j = 0; j < 4; j++) {
            wmma::store_matrix_sync(&Cs[warp][0][0], acc[i][j], 20, wmma::mem_row_major);
            __syncwarp();
            int r = row0 + wm * 32 + i * 16 + rr;
            int c0l = col0 + wn * 64 + j * 16 + cc;
            float* dst = C + (size_t)r * N + c0l;
#pragma unroll
            for (int e = 0; e < 8; e++) {
                int c = c0l + e;
                if (ALIGN4 || c < N) {
                    float vv = Cs[warp][rr][cc + e];
                    if (EPI >= 1) vv += bias[c];
                    if (EPI == 2) vv = 0.5f * vv * (1.0f + erff(vv * 0.70710678118654752f));
                    dst[e] = vv;
                }
            }
            __syncwarp();
        }
    }
}

template <int EPI, bool ALIGN4>
__global__ void __launch_bounds__(256)
gemm_tf32_kernel(const float* __restrict__ A, const float* __restrict__ Bm,
                 const float* __restrict__ bias, float* __restrict__ C,
                 int M, int N, int K) {
    gemm_body<EPI, ALIGN4>(A, Bm, bias, C, M, N, K);
}

// Batched QKV: blockIdx.z selects weight + output (q/k/v contiguous in ws)
__global__ void __launch_bounds__(256)
gemm_qkv_kernel(const float* __restrict__ A, const float* __restrict__ w0,
                const float* __restrict__ w1, const float* __restrict__ w2,
                float* __restrict__ c0) {
    const float* Bm = (blockIdx.z == 0) ? w0 : (blockIdx.z == 1) ? w1 : w2;
    float* C = c0 + (size_t)blockIdx.z * Tq * Dq;
    gemm_body<0, true>(A, Bm, nullptr, C, Tq, Dq, Dq);
}

// ---------------------------------------------------------------------------
// Attention scores (TF32 wmma): out[bh,q,k] = scale*dot(q,k), mask -> -inf
// grid (S/64, S/64, B*H), 256 threads. 8 warps: 4 in M (16 rows) x 2 in N (32 cols)
// ---------------------------------------------------------------------------
__global__ void __launch_bounds__(256)
attn_scores_tf32(const float* __restrict__ q, const float* __restrict__ k,
                 const int* __restrict__ mask, float* __restrict__ out) {
    __shared__ float Qs[64][68];
    __shared__ float Ks[64][68];
    __shared__ float Cs[8][16][20];
    int bh = blockIdx.z;
    int b = bh / Hq, h = bh % Hq;
    int q0 = blockIdx.y * 64, k0 = blockIdx.x * 64;
    int tid = threadIdx.x;

#pragma unroll
    for (int i = 0; i < 4; i++) {
        int idx = tid + i * 256;
        int r = idx >> 4;
        int c4 = (idx & 15) * 4;
        float4 qv = *(const float4*)(q + (size_t)(b * Sq + q0 + r) * Dq + h * HDq + c4);
        Qs[r][c4 + 0] = T32(qv.x); Qs[r][c4 + 1] = T32(qv.y);
        Qs[r][c4 + 2] = T32(qv.z); Qs[r][c4 + 3] = T32(qv.w);
        float4 kv = *(const float4*)(k + (size_t)(b * Sq + k0 + r) * Dq + h * HDq + c4);
        Ks[r][c4 + 0] = T32(kv.x); Ks[r][c4 + 1] = T32(kv.y);
        Ks[r][c4 + 2] = T32(kv.z); Ks[r][c4 + 3] = T32(kv.w);
    }
    __syncthreads();

    int warp = tid >> 5, lane = tid & 31;
    int wm = warp & 3, wn = warp >> 2;

    wmma::fragment<wmma::accumulator, 16, 16, 8, float> acc[2];
    wmma::fill_fragment(acc[0], 0.0f);
    wmma::fill_fragment(acc[1], 0.0f);

#pragma unroll
    for (int kk = 0; kk < 8; kk++) {
        wmma::fragment<wmma::matrix_a, 16, 16, 8, wmma::precision::tf32, wmma::row_major> af;
        wmma::load_matrix_sync(af, &Qs[wm * 16][kk * 8], 68);
#pragma unroll
        for (int j = 0; j < 2; j++) {
            wmma::fragment<wmma::matrix_b, 16, 16, 8, wmma::precision::tf32, wmma::col_major> bf;
            wmma::load_matrix_sync(bf, &Ks[wn * 32 + j * 16][kk * 8], 68);
            wmma::mma_sync(acc[j], af, bf, acc[j]);
        }
    }

    const float scale = 0.03608439182435161f;  // 1/sqrt(D=768)
    int rr = lane >> 1, cc = (lane & 1) * 8;
#pragma unroll
    for (int j = 0; j < 2; j++) {
        wmma::store_matrix_sync(&Cs[warp][0][0], acc[j], 20, wmma::mem_row_major);
        __syncwarp();
        int qr = q0 + wm * 16 + rr;
        int kc0 = k0 + wn * 32 + j * 16 + cc;
        float* dst = out + ((size_t)bh * Sq + qr) * Sq + kc0;
#pragma unroll
        for (int e = 0; e < 8; e++) {
            float vv = Cs[warp][rr][cc + e] * scale;
            if (mask[b * Sq + kc0 + e] == 0) vv = -INFINITY;
            dst[e] = vv;
        }
        __syncwarp();
    }
}

// ---------------------------------------------------------------------------
// In-place softmax over last dim (512). One warp per row, 16 elems/lane.
// ---------------------------------------------------------------------------
__global__ void softmax_kernel(float* __restrict__ p) {
    int row = blockIdx.x * 4 + (threadIdx.x >> 5);
    int lane = threadIdx.x & 31;
    float* r = p + (size_t)row * Sq;
    float v[16];
    float m = -INFINITY;
#pragma unroll
    for (int i = 0; i < 16; i++) {
        v[i] = r[lane + i * 32];
        m = fmaxf(m, v[i]);
    }
#pragma unroll
    for (int o = 16; o > 0; o >>= 1) m = fmaxf(m, __shfl_xor_sync(0xffffffffu, m, o));
    float s = 0.f;
#pragma unroll
    for (int i = 0; i < 16; i++) {
        v[i] = __expf(v[i] - m);
        s += v[i];
    }
#pragma unroll
    for (int o = 16; o > 0; o >>= 1) s += __shfl_xor_sync(0xffffffffu, s, o);
    float inv = 1.0f / s;
#pragma unroll
    for (int i = 0; i < 16; i++) r[lane + i * 32] = v[i] * inv;
}

// ---------------------------------------------------------------------------
// o[b,q,h*64+d] = sum_k P[bh,q,k] * V[b,k,h*64+d]   (TF32 wmma)
// grid (1, S/64, B*H). 8 warps: 4 in M x 2 in N (32 d-cols each)
// ---------------------------------------------------------------------------
__global__ void __launch_bounds__(256)
attn_av_tf32(const float* __restrict__ p, const float* __restrict__ v,
             float* __restrict__ o) {
    __shared__ float Ps[64][36];
    __shared__ float Vs[32][68];
    __shared__ float Cs[8][16][20];
    int bh = blockIdx.z;
    int b = bh / Hq, h = bh % Hq;
    int q0 = blockIdx.y * 64;
    int tid = threadIdx.x;
    int warp = tid >> 5, lane = tid & 31;
    int wm = warp & 3, wn = warp >> 2;

    wmma::fragment<wmma::accumulator, 16, 16, 8, float> acc[2];
    wmma::fill_fragment(acc[0], 0.0f);
    wmma::fill_fragment(acc[1], 0.0f);

    for (int k0 = 0; k0 < Sq; k0 += 32) {
#pragma unroll
        for (int i = 0; i < 2; i++) {
            int idx = tid + i * 256;
            int pr = idx >> 3, pc4 = (idx & 7) * 4;
            float4 pv = *(const float4*)(p + ((size_t)bh * Sq + q0 + pr) * Sq + k0 + pc4);
            Ps[pr][pc4 + 0] = T32(pv.x); Ps[pr][pc4 + 1] = T32(pv.y);
            Ps[pr][pc4 + 2] = T32(pv.z); Ps[pr][pc4 + 3] = T32(pv.w);
            int vr = idx >> 4, vc4 = (idx & 15) * 4;
            float4 vv = *(const float4*)(v + (size_t)(b * Sq + k0 + vr) * Dq + h * HDq + vc4);
            Vs[vr][vc4 + 0] = T32(vv.x); Vs[vr][vc4 + 1] = T32(vv.y);
            Vs[vr][vc4 + 2] = T32(vv.z); Vs[vr][vc4 + 3] = T32(vv.w);
        }
        __syncthreads();
#pragma unroll
        for (int kk = 0; kk < 4; kk++) {
            wmma::fragment<wmma::matrix_a, 16, 16, 8, wmma::precision::tf32, wmma::row_major> af;
            wmma::load_matrix_sync(af, &Ps[wm * 16][kk * 8], 36);
#pragma unroll
            for (int j = 0; j < 2; j++) {
                wmma::fragment<wmma::matrix_b, 16, 16, 8, wmma::precision::tf32, wmma::row_major> bf;
                wmma::load_matrix_sync(bf, &Vs[kk * 8][wn * 32 + j * 16], 68);
                wmma::mma_sync(acc[j], af, bf, acc[j]);
            }
        }
        __syncthreads();
    }

    int rr = lane >> 1, cc = (lane & 1) * 8;
#pragma unroll
    for (int j = 0; j < 2; j++) {
        wmma::store_matrix_sync(&Cs[warp][0][0], acc[j], 20, wmma::mem_row_major);
        __syncwarp();
        int qr = q0 + wm * 16 + rr;
        int dc = h * HDq + wn * 32 + j * 16 + cc;
        float* dst = o + (size_t)(b * Sq + qr) * Dq + dc;
#pragma unroll
        for (int e = 0; e < 8; e++) dst[e] = Cs[warp][rr][cc + e];
        __syncwarp();
    }
}

// ---------------------------------------------------------------------------
// Host orchestration (graph-capturable: kernel launches only)
// ---------------------------------------------------------------------------
extern "C" void kernel_launch(void* const* d_in, const int* in_sizes, int n_in,
                              void* d_out, int out_size) {
    const int*   ids  = (const int*)d_in[0];
    const int*   mask = (const int*)d_in[1];
    const float* wemb = (const float*)d_in[2];
    const float* pemb = (const float*)d_in[3];
    const float* semb = (const float*)d_in[4];
    const float* elng = (const float*)d_in[5];
    const float* elnb = (const float*)d_in[6];
    const float* Wq   = (const float*)d_in[7];
    const float* Wk   = (const float*)d_in[8];
    const float* Wv   = (const float*)d_in[9];
    const float* Wo   = (const float*)d_in[10];
    const float* f1w  = (const float*)d_in[11];
    const float* f1b  = (const float*)d_in[12];
    const float* f2w  = (const float*)d_in[13];
    const float* f2b  = (const float*)d_in[14];
    const float* l1g  = (const float*)d_in[15];
    const float* l1b  = (const float*)d_in[16];
    const float* l2g  = (const float*)d_in[17];
    const float* l2b  = (const float*)d_in[18];
    const float* outw = (const float*)d_in[19];
    const float* outb = (const float*)d_in[20];

    float* ws = nullptr;
    cudaGetSymbolAddress((void**)&ws, g_ws);
    float* x  = ws;
    float* q  = ws + 1 * (size_t)Tq * Dq;
    float* kb = ws + 2 * (size_t)Tq * Dq;
    float* vb = ws + 3 * (size_t)Tq * Dq;
    float* tb = ws + 4 * (size_t)Tq * Dq;
    float* x1 = ws + 5 * (size_t)Tq * Dq;
    float* hb = ws + 6 * (size_t)Tq * Dq;

    float* logits = (float*)d_out;                       // [B*S, V]
    float* attn   = logits + (size_t)Tq * Vq;            // [L, B*H, S, S]

    embed_ln_kernel<<<Tq, 256>>>(ids, wemb, pemb, semb, elng, elnb, x);

    for (int l = 0; l < Lq; l++) {
        float* slab = attn + (size_t)l * Bq * Hq * Sq * Sq;
        dim3 gDD(Dq / 128, Tq / 128);  // (6,16)

        gemm_qkv_kernel<<<dim3(Dq / 128, Tq / 128, 3), 256>>>(
            x, Wq + (size_t)l * Dq * Dq, Wk + (size_t)l * Dq * Dq,
            Wv + (size_t)l * Dq * Dq, q);

        attn_scores_tf32<<<dim3(Sq / 64, Sq / 64, Bq * Hq), 256>>>(q, kb, mask, slab);
        softmax_kernel<<<Bq * Hq * Sq / 4, 128>>>(slab);
        attn_av_tf32<<<dim3(1, Sq / 64, Bq * Hq), 256>>>(slab, vb, tb);

        gemm_tf32_kernel<0, true><<<gDD, 256>>>(tb, Wo + (size_t)l * Dq * Dq, nullptr, q, Tq, Dq, Dq);
        add_ln_kernel<<<Tq, 256>>>(x, q, l1g + (size_t)l * Dq, l1b + (size_t)l * Dq, x1);

        gemm_tf32_kernel<2, true><<<dim3(Fq / 128, Tq / 128), 256>>>(
            x1, f1w + (size_t)l * Dq * Fq, f1b + (size_t)l * Fq, hb, Tq, Fq, Dq);
        gemm_tf32_kernel<1, true><<<dim3(Dq / 128, Tq / 128), 256>>>(
            hb, f2w + (size_t)l * Fq * Dq, f2b + (size_t)l * Dq, tb, Tq, Dq, Fq);
        add_ln_kernel<<<Tq, 256>>>(x1, tb, l2g + (size_t)l * Dq, l2b + (size_t)l * Dq, x);
    }

    gemm_tf32_kernel<1, false><<<dim3((Vq + 127) / 128, Tq / 128), 256>>>(
        x, outw, outb, logits, Tq, Vq, Dq);
}

// round 7
// speedup vs baseline: 1.0292x; 1.0292x over previous
#include <cuda_runtime.h>
#include <mma.h>
#include <math.h>

using namespace nvcuda;

// BERT-base forward: B=4, S=512, L=12, D=768, H=12, F=3072, V=30522
#define Bq 4
#define Sq 512
#define Lq 12
#define Dq 768
#define Hq 12
#define Fq 3072
#define Vq 30522
#define HDq 64
#define Tq 2048    // B*S tokens
#define Npad 30592 // 239*128, padded vocab width

// Workspace: x,q,k,v,t,x1 [T,D] + h [T,F] + padded vocab W/bias
__device__ float g_ws[6 * (size_t)Tq * Dq + (size_t)Tq * Fq
                      + (size_t)Dq * Npad + Npad];

__device__ __forceinline__ float T32(float x) { return wmma::__float_to_tf32(x); }

// ---------------------------------------------------------------------------
// Block-wide sum of (a,b) pairs, 256 threads
// ---------------------------------------------------------------------------
__device__ __forceinline__ float2 blockReduce2(float a, float b) {
#pragma unroll
    for (int o = 16; o > 0; o >>= 1) {
        a += __shfl_down_sync(0xffffffffu, a, o);
        b += __shfl_down_sync(0xffffffffu, b, o);
    }
    __shared__ float2 sh[8];
    int lane = threadIdx.x & 31, wid = threadIdx.x >> 5;
    if (lane == 0) sh[wid] = make_float2(a, b);
    __syncthreads();
    if (wid == 0) {
        float2 v = (lane < 8) ? sh[lane] : make_float2(0.f, 0.f);
#pragma unroll
        for (int o = 4; o > 0; o >>= 1) {
            v.x += __shfl_down_sync(0xffffffffu, v.x, o);
            v.y += __shfl_down_sync(0xffffffffu, v.y, o);
        }
        if (lane == 0) sh[0] = v;
    }
    __syncthreads();
    return sh[0];
}

// ---------------------------------------------------------------------------
// Embedding + LayerNorm: one block per token
// ---------------------------------------------------------------------------
__global__ void embed_ln_kernel(const int* __restrict__ ids,
                                const float* __restrict__ wemb,
                                const float* __restrict__ pemb,
                                const float* __restrict__ semb,
                                const float* __restrict__ g,
                                const float* __restrict__ bta,
                                float* __restrict__ x) {
    int t = blockIdx.x;
    int s = t & (Sq - 1);
    int id = ids[t];
    float v[3];
    float sum = 0.f, sq = 0.f;
#pragma unroll
    for (int i = 0; i < 3; i++) {
        int d = threadIdx.x + i * 256;
        float val = wemb[(size_t)id * Dq + d] + pemb[(size_t)s * Dq + d] + semb[d];
        v[i] = val;
        sum += val;
        sq += val * val;
    }
    float2 r = blockReduce2(sum, sq);
    float mu = r.x * (1.0f / Dq);
    float var = r.y * (1.0f / Dq) - mu * mu;
    float rstd = rsqrtf(var + 1e-5f);
#pragma unroll
    for (int i = 0; i < 3; i++) {
        int d = threadIdx.x + i * 256;
        x[(size_t)t * Dq + d] = (v[i] - mu) * rstd * g[d] + bta[d];
    }
}

// ---------------------------------------------------------------------------
// out = LayerNorm(a + bvec) * g + beta : one block per token
// ---------------------------------------------------------------------------
__global__ void add_ln_kernel(const float* __restrict__ a,
                              const float* __restrict__ bvec,
                              const float* __restrict__ g,
                              const float* __restrict__ bta,
                              float* __restrict__ out) {
    int t = blockIdx.x;
    float v[3];
    float sum = 0.f, sq = 0.f;
#pragma unroll
    for (int i = 0; i < 3; i++) {
        int d = threadIdx.x + i * 256;
        float val = a[(size_t)t * Dq + d] + bvec[(size_t)t * Dq + d];
        v[i] = val;
        sum += val;
        sq += val * val;
    }
    float2 r = blockReduce2(sum, sq);
    float mu = r.x * (1.0f / Dq);
    float var = r.y * (1.0f / Dq) - mu * mu;
    float rstd = rsqrtf(var + 1e-5f);
#pragma unroll
    for (int i = 0; i < 3; i++) {
        int d = threadIdx.x + i * 256;
        out[(size_t)t * Dq + d] = (v[i] - mu) * rstd * g[d] + bta[d];
    }
}

// ---------------------------------------------------------------------------
// Pad vocab weight [D, V] -> [D, Npad] and bias [V] -> [Npad] (zeros in pad)
// ---------------------------------------------------------------------------
__global__ void pad_vocab_kernel(const float* __restrict__ w,
                                 float* __restrict__ wp) {
    size_t gid = (size_t)blockIdx.x * 256 + threadIdx.x;
    size_t i4 = gid * 4;
    if (i4 >= (size_t)Dq * Npad) return;
    int k = (int)(i4 / Npad);
    int c = (int)(i4 % Npad);
    float4 v;
    v.x = (c + 0 < Vq) ? w[(size_t)k * Vq + c + 0] : 0.f;
    v.y = (c + 1 < Vq) ? w[(size_t)k * Vq + c + 1] : 0.f;
    v.z = (c + 2 < Vq) ? w[(size_t)k * Vq + c + 2] : 0.f;
    v.w = (c + 3 < Vq) ? w[(size_t)k * Vq + c + 3] : 0.f;
    *(float4*)(wp + i4) = v;
}

__global__ void pad_bias_kernel(const float* __restrict__ b,
                                float* __restrict__ bp) {
    int c = blockIdx.x * 256 + threadIdx.x;
    if (c < Npad) bp[c] = (c < Vq) ? b[c] : 0.f;
}

// ---------------------------------------------------------------------------
// TF32 WMMA GEMM body: C[M,N] = A[M,K] @ B[K,N], row-major, ldB = B row stride.
// 128x128 block tile, BK=32, 8 warps (4 in M x 2 in N), warp tile 32x64.
// Global->register prefetch pipeline over the k-slabs.
// EPI: 0=none (direct fragment store, needs N%16==0 and full tiles),
//      1=+bias, 2=+bias then exact GELU (staged via smem, col-bound checked).
// Requires: M%128==0, K%32==0, loads of B always in-range (ldB >= gridN*128).
// ---------------------------------------------------------------------------
template <int EPI>
__device__ __forceinline__ void gemm_body(const float* __restrict__ A,
                                          const float* __restrict__ Bm,
                                          const float* __restrict__ bias,
                                          float* __restrict__ C,
                                          int N, int K, int ldB) {
    __shared__ float As[128][36];
    __shared__ float Bs[32][132];
    __shared__ float Cs[8][16][20];

    int tid = threadIdx.x;
    int row0 = blockIdx.y * 128, col0 = blockIdx.x * 128;
    int warp = tid >> 5, lane = tid & 31;
    int wm = warp & 3, wn = warp >> 2;

    wmma::fragment<wmma::accumulator, 16, 16, 8, float> acc[2][4];
#pragma unroll
    for (int i = 0; i < 2; i++)
#pragma unroll
        for (int j = 0; j < 4; j++)
            wmma::fill_fragment(acc[i][j], 0.0f);

    int aRow = tid >> 3;
    int aCol = (tid & 7) * 4;
    int bRow = tid >> 5;
    int bCol = (tid & 31) * 4;

    const float* aPtr = A + (size_t)(row0 + aRow) * K + aCol;
    const float* bPtr = Bm + (size_t)bRow * ldB + col0 + bCol;

    float4 aR[4], bR[4];
#pragma unroll
    for (int it = 0; it < 4; it++) {
        aR[it] = *(const float4*)(aPtr + (size_t)it * 32 * K);
        bR[it] = *(const float4*)(bPtr + (size_t)it * 8 * ldB);
    }

    for (int k0 = 0; k0 < K; k0 += 32) {
#pragma unroll
        for (int it = 0; it < 4; it++) {
            int r = aRow + it * 32;
            As[r][aCol + 0] = T32(aR[it].x);
            As[r][aCol + 1] = T32(aR[it].y);
            As[r][aCol + 2] = T32(aR[it].z);
            As[r][aCol + 3] = T32(aR[it].w);
            int rb = bRow + it * 8;
            Bs[rb][bCol + 0] = T32(bR[it].x);
            Bs[rb][bCol + 1] = T32(bR[it].y);
            Bs[rb][bCol + 2] = T32(bR[it].z);
            Bs[rb][bCol + 3] = T32(bR[it].w);
        }
        __syncthreads();

        if (k0 + 32 < K) {
#pragma unroll
            for (int it = 0; it < 4; it++) {
                aR[it] = *(const float4*)(aPtr + (k0 + 32) + (size_t)it * 32 * K);
                bR[it] = *(const float4*)(bPtr + (size_t)(k0 + 32 + it * 8) * ldB);
            }
        }

#pragma unroll
        for (int kk = 0; kk < 4; kk++) {
            wmma::fragment<wmma::matrix_a, 16, 16, 8, wmma::precision::tf32, wmma::row_major> af[2];
            wmma::fragment<wmma::matrix_b, 16, 16, 8, wmma::precision::tf32, wmma::row_major> bf[4];
#pragma unroll
            for (int i = 0; i < 2; i++)
                wmma::load_matrix_sync(af[i], &As[wm * 32 + i * 16][kk * 8], 36);
#pragma unroll
            for (int j = 0; j < 4; j++)
                wmma::load_matrix_sync(bf[j], &Bs[kk * 8][wn * 64 + j * 16], 132);
#pragma unroll
            for (int i = 0; i < 2; i++)
#pragma unroll
                for (int j = 0; j < 4; j++)
                    wmma::mma_sync(acc[i][j], af[i], bf[j], acc[i][j]);
        }
        __syncthreads();
    }

    if (EPI == 0) {
        // direct fragment store (full tiles, N % 16 == 0)
#pragma unroll
        for (int i = 0; i < 2; i++)
#pragma unroll
            for (int j = 0; j < 4; j++) {
                float* dst = C + (size_t)(row0 + wm * 32 + i * 16) * N
                               + col0 + wn * 64 + j * 16;
                wmma::store_matrix_sync(dst, acc[i][j], N, wmma::mem_row_major);
            }
    } else {
        int rr = lane >> 1, cc = (lane & 1) * 8;
#pragma unroll
        for (int i = 0; i < 2; i++) {
#pragma unroll
            for (int j = 0; j < 4; j++) {
                wmma::store_matrix_sync(&Cs[warp][0][0], acc[i][j], 20, wmma::mem_row_major);
                __syncwarp();
                int r = row0 + wm * 32 + i * 16 + rr;
                int c0l = col0 + wn * 64 + j * 16 + cc;
                float* dst = C + (size_t)r * N + c0l;
#pragma unroll
                for (int e = 0; e < 8; e++) {
                    int c = c0l + e;
                    if (c < N) {
                        float vv = Cs[warp][rr][cc + e];
                        vv += bias[c];
                        if (EPI == 2) vv = 0.5f * vv * (1.0f + erff(vv * 0.70710678118654752f));
                        dst[e] = vv;
                    }
                }
                __syncwarp();
            }
        }
    }
}

template <int EPI>
__global__ void __launch_bounds__(256)
gemm_tf32_kernel(const float* __restrict__ A, const float* __restrict__ Bm,
                 const float* __restrict__ bias, float* __restrict__ C,
                 int N, int K, int ldB) {
    gemm_body<EPI>(A, Bm, bias, C, N, K, ldB);
}

// Batched QKV: blockIdx.z selects weight + output (q/k/v contiguous in ws)
__global__ void __launch_bounds__(256)
gemm_qkv_kernel(const float* __restrict__ A, const float* __restrict__ w0,
                const float* __restrict__ w1, const float* __restrict__ w2,
                float* __restrict__ c0) {
    const float* Bm = (blockIdx.z == 0) ? w0 : (blockIdx.z == 1) ? w1 : w2;
    float* C = c0 + (size_t)blockIdx.z * Tq * Dq;
    gemm_body<0>(A, Bm, nullptr, C, Dq, Dq, Dq);
}

// ---------------------------------------------------------------------------
// Attention scores (TF32 wmma): out[bh,q,k] = scale*dot(q,k), mask -> -inf
// ---------------------------------------------------------------------------
__global__ void __launch_bounds__(256)
attn_scores_tf32(const float* __restrict__ q, const float* __restrict__ k,
                 const int* __restrict__ mask, float* __restrict__ out) {
    __shared__ float Qs[64][68];
    __shared__ float Ks[64][68];
    __shared__ float Cs[8][16][20];
    int bh = blockIdx.z;
    int b = bh / Hq, h = bh % Hq;
    int q0 = blockIdx.y * 64, k0 = blockIdx.x * 64;
    int tid = threadIdx.x;

#pragma unroll
    for (int i = 0; i < 4; i++) {
        int idx = tid + i * 256;
        int r = idx >> 4;
        int c4 = (idx & 15) * 4;
        float4 qv = *(const float4*)(q + (size_t)(b * Sq + q0 + r) * Dq + h * HDq + c4);
        Qs[r][c4 + 0] = T32(qv.x); Qs[r][c4 + 1] = T32(qv.y);
        Qs[r][c4 + 2] = T32(qv.z); Qs[r][c4 + 3] = T32(qv.w);
        float4 kv = *(const float4*)(k + (size_t)(b * Sq + k0 + r) * Dq + h * HDq + c4);
        Ks[r][c4 + 0] = T32(kv.x); Ks[r][c4 + 1] = T32(kv.y);
        Ks[r][c4 + 2] = T32(kv.z); Ks[r][c4 + 3] = T32(kv.w);
    }
    __syncthreads();

    int warp = tid >> 5, lane = tid & 31;
    int wm = warp & 3, wn = warp >> 2;

    wmma::fragment<wmma::accumulator, 16, 16, 8, float> acc[2];
    wmma::fill_fragment(acc[0], 0.0f);
    wmma::fill_fragment(acc[1], 0.0f);

#pragma unroll
    for (int kk = 0; kk < 8; kk++) {
        wmma::fragment<wmma::matrix_a, 16, 16, 8, wmma::precision::tf32, wmma::row_major> af;
        wmma::load_matrix_sync(af, &Qs[wm * 16][kk * 8], 68);
#pragma unroll
        for (int j = 0; j < 2; j++) {
            wmma::fragment<wmma::matrix_b, 16, 16, 8, wmma::precision::tf32, wmma::col_major> bf;
            wmma::load_matrix_sync(bf, &Ks[wn * 32 + j * 16][kk * 8], 68);
            wmma::mma_sync(acc[j], af, bf, acc[j]);
        }
    }

    const float scale = 0.03608439182435161f;  // 1/sqrt(D=768)
    int rr = lane >> 1, cc = (lane & 1) * 8;
#pragma unroll
    for (int j = 0; j < 2; j++) {
        wmma::store_matrix_sync(&Cs[warp][0][0], acc[j], 20, wmma::mem_row_major);
        __syncwarp();
        int qr = q0 + wm * 16 + rr;
        int kc0 = k0 + wn * 32 + j * 16 + cc;
        float* dst = out + ((size_t)bh * Sq + qr) * Sq + kc0;
#pragma unroll
        for (int e = 0; e < 8; e++) {
            float vv = Cs[warp][rr][cc + e] * scale;
            if (mask[b * Sq + kc0 + e] == 0) vv = -INFINITY;
            dst[e] = vv;
        }
        __syncwarp();
    }
}

// ---------------------------------------------------------------------------
// In-place softmax over last dim (512). One warp per row.
// ---------------------------------------------------------------------------
__global__ void softmax_kernel(float* __restrict__ p) {
    int row = blockIdx.x * 4 + (threadIdx.x >> 5);
    int lane = threadIdx.x & 31;
    float* r = p + (size_t)row * Sq;
    float v[16];
    float m = -INFINITY;
#pragma unroll
    for (int i = 0; i < 16; i++) {
        v[i] = r[lane + i * 32];
        m = fmaxf(m, v[i]);
    }
#pragma unroll
    for (int o = 16; o > 0; o >>= 1) m = fmaxf(m, __shfl_xor_sync(0xffffffffu, m, o));
    float s = 0.f;
#pragma unroll
    for (int i = 0; i < 16; i++) {
        v[i] = __expf(v[i] - m);
        s += v[i];
    }
#pragma unroll
    for (int o = 16; o > 0; o >>= 1) s += __shfl_xor_sync(0xffffffffu, s, o);
    float inv = 1.0f / s;
#pragma unroll
    for (int i = 0; i < 16; i++) r[lane + i * 32] = v[i] * inv;
}

// ---------------------------------------------------------------------------
// o[b,q,h*64+d] = sum_k P[bh,q,k] * V[b,k,h*64+d]   (TF32 wmma)
// ---------------------------------------------------------------------------
__global__ void __launch_bounds__(256)
attn_av_tf32(const float* __restrict__ p, const float* __restrict__ v,
             float* __restrict__ o) {
    __shared__ float Ps[64][36];
    __shared__ float Vs[32][68];
    __shared__ float Cs[8][16][20];
    int bh = blockIdx.z;
    int b = bh / Hq, h = bh % Hq;
    int q0 = blockIdx.y * 64;
    int tid = threadIdx.x;
    int warp = tid >> 5, lane = tid & 31;
    int wm = warp & 3, wn = warp >> 2;

    wmma::fragment<wmma::accumulator, 16, 16, 8, float> acc[2];
    wmma::fill_fragment(acc[0], 0.0f);
    wmma::fill_fragment(acc[1], 0.0f);

    for (int k0 = 0; k0 < Sq; k0 += 32) {
#pragma unroll
        for (int i = 0; i < 2; i++) {
            int idx = tid + i * 256;
            int pr = idx >> 3, pc4 = (idx & 7) * 4;
            float4 pv = *(const float4*)(p + ((size_t)bh * Sq + q0 + pr) * Sq + k0 + pc4);
            Ps[pr][pc4 + 0] = T32(pv.x); Ps[pr][pc4 + 1] = T32(pv.y);
            Ps[pr][pc4 + 2] = T32(pv.z); Ps[pr][pc4 + 3] = T32(pv.w);
            int vr = idx >> 4, vc4 = (idx & 15) * 4;
            float4 vv = *(const float4*)(v + (size_t)(b * Sq + k0 + vr) * Dq + h * HDq + vc4);
            Vs[vr][vc4 + 0] = T32(vv.x); Vs[vr][vc4 + 1] = T32(vv.y);
            Vs[vr][vc4 + 2] = T32(vv.z); Vs[vr][vc4 + 3] = T32(vv.w);
        }
        __syncthreads();
#pragma unroll
        for (int kk = 0; kk < 4; kk++) {
            wmma::fragment<wmma::matrix_a, 16, 16, 8, wmma::precision::tf32, wmma::row_major> af;
            wmma::load_matrix_sync(af, &Ps[wm * 16][kk * 8], 36);
#pragma unroll
            for (int j = 0; j < 2; j++) {
                wmma::fragment<wmma::matrix_b, 16, 16, 8, wmma::precision::tf32, wmma::row_major> bf;
                wmma::load_matrix_sync(bf, &Vs[kk * 8][wn * 32 + j * 16], 68);
                wmma::mma_sync(acc[j], af, bf, acc[j]);
            }
        }
        __syncthreads();
    }

    int rr = lane >> 1, cc = (lane & 1) * 8;
#pragma unroll
    for (int j = 0; j < 2; j++) {
        wmma::store_matrix_sync(&Cs[warp][0][0], acc[j], 20, wmma::mem_row_major);
        __syncwarp();
        int qr = q0 + wm * 16 + rr;
        int dc = h * HDq + wn * 32 + j * 16 + cc;
        float* dst = o + (size_t)(b * Sq + qr) * Dq + dc;
#pragma unroll
        for (int e = 0; e < 8; e++) dst[e] = Cs[warp][rr][cc + e];
        __syncwarp();
    }
}

// ---------------------------------------------------------------------------
// Host orchestration (graph-capturable: kernel launches only)
// ---------------------------------------------------------------------------
extern "C" void kernel_launch(void* const* d_in, const int* in_sizes, int n_in,
                              void* d_out, int out_size) {
    const int*   ids  = (const int*)d_in[0];
    const int*   mask = (const int*)d_in[1];
    const float* wemb = (const float*)d_in[2];
    const float* pemb = (const float*)d_in[3];
    const float* semb = (const float*)d_in[4];
    const float* elng = (const float*)d_in[5];
    const float* elnb = (const float*)d_in[6];
    const float* Wq   = (const float*)d_in[7];
    const float* Wk   = (const float*)d_in[8];
    const float* Wv   = (const float*)d_in[9];
    const float* Wo   = (const float*)d_in[10];
    const float* f1w  = (const float*)d_in[11];
    const float* f1b  = (const float*)d_in[12];
    const float* f2w  = (const float*)d_in[13];
    const float* f2b  = (const float*)d_in[14];
    const float* l1g  = (const float*)d_in[15];
    const float* l1b  = (const float*)d_in[16];
    const float* l2g  = (const float*)d_in[17];
    const float* l2b  = (const float*)d_in[18];
    const float* outw = (const float*)d_in[19];
    const float* outb = (const float*)d_in[20];

    float* ws = nullptr;
    cudaGetSymbolAddress((void**)&ws, g_ws);
    float* x  = ws;
    float* q  = ws + 1 * (size_t)Tq * Dq;
    float* kb = ws + 2 * (size_t)Tq * Dq;
    float* vb = ws + 3 * (size_t)Tq * Dq;
    float* tb = ws + 4 * (size_t)Tq * Dq;
    float* x1 = ws + 5 * (size_t)Tq * Dq;
    float* hb = ws + 6 * (size_t)Tq * Dq;
    float* wpad = hb + (size_t)Tq * Fq;
    float* bpad = wpad + (size_t)Dq * Npad;

    float* logits = (float*)d_out;                       // [B*S, V]
    float* attn   = logits + (size_t)Tq * Vq;            // [L, B*H, S, S]

    // pad vocab weight/bias (overlaps with encoder work on the stream order)
    {
        size_t n4 = ((size_t)Dq * Npad) / 4;
        pad_vocab_kernel<<<(unsigned)((n4 + 255) / 256), 256>>>(outw, wpad);
        pad_bias_kernel<<<(Npad + 255) / 256, 256>>>(outb, bpad);
    }

    embed_ln_kernel<<<Tq, 256>>>(ids, wemb, pemb, semb, elng, elnb, x);

    for (int l = 0; l < Lq; l++) {
        float* slab = attn + (size_t)l * Bq * Hq * Sq * Sq;
        dim3 gDD(Dq / 128, Tq / 128);  // (6,16)

        gemm_qkv_kernel<<<dim3(Dq / 128, Tq / 128, 3), 256>>>(
            x, Wq + (size_t)l * Dq * Dq, Wk + (size_t)l * Dq * Dq,
            Wv + (size_t)l * Dq * Dq, q);

        attn_scores_tf32<<<dim3(Sq / 64, Sq / 64, Bq * Hq), 256>>>(q, kb, mask, slab);
        softmax_kernel<<<Bq * Hq * Sq / 4, 128>>>(slab);
        attn_av_tf32<<<dim3(1, Sq / 64, Bq * Hq), 256>>>(slab, vb, tb);

        gemm_tf32_kernel<0><<<gDD, 256>>>(tb, Wo + (size_t)l * Dq * Dq, nullptr, q,
                                          Dq, Dq, Dq);
        add_ln_kernel<<<Tq, 256>>>(x, q, l1g + (size_t)l * Dq, l1b + (size_t)l * Dq, x1);

        gemm_tf32_kernel<2><<<dim3(Fq / 128, Tq / 128), 256>>>(
            x1, f1w + (size_t)l * Dq * Fq, f1b + (size_t)l * Fq, hb, Fq, Dq, Fq);
        gemm_tf32_kernel<1><<<dim3(Dq / 128, Tq / 128), 256>>>(
            hb, f2w + (size_t)l * Fq * Dq, f2b + (size_t)l * Dq, tb, Dq, Fq, Dq);
        add_ln_kernel<<<Tq, 256>>>(x1, tb, l2g + (size_t)l * Dq, l2b + (size_t)l * Dq, x);
    }

    gemm_tf32_kernel<1><<<dim3(Npad / 128, Tq / 128), 256>>>(
        x, wpad, bpad, logits, Vq, Dq, Npad);
}

// round 9
// speedup vs baseline: 1.1855x; 1.1519x over previous
#include <cuda_runtime.h>
#include <mma.h>
#include <math.h>
#include <cstdint>

using namespace nvcuda;

// BERT-base forward: B=4, S=512, L=12, D=768, H=12, F=3072, V=30522
#define Bq 4
#define Sq 512
#define Lq 12
#define Dq 768
#define Hq 12
#define Fq 3072
#define Vq 30522
#define HDq 64
#define Tq 2048    // B*S tokens
#define Npad 30592 // 239*128, padded vocab width

#define LDD ((size_t)Lq * Dq * Dq)
#define LDF ((size_t)Lq * Dq * Fq)

// Workspace: activations + padded vocab + TF32-preconverted weights
// x,q,kb,vb,tb,x1 [T,D]; hb [T,F]; wpad [D,Npad]; bpad [Npad];
// cWq,cWk,cWv,cWo [L,D,D]; cF1 [L,D,F]; cF2 [L,F,D]
__device__ float g_ws[6 * (size_t)Tq * Dq + (size_t)Tq * Fq
                      + (size_t)Dq * Npad + Npad
                      + 4 * LDD + 2 * LDF];

__device__ __forceinline__ float T32(float x) { return wmma::__float_to_tf32(x); }

__device__ __forceinline__ void cp16(uint32_t dst, const float* src) {
    asm volatile("cp.async.cg.shared.global [%0], [%1], 16;" :: "r"(dst), "l"(src));
}
__device__ __forceinline__ void cp_commit() {
    asm volatile("cp.async.commit_group;");
}
template <int N>
__device__ __forceinline__ void cp_wait() {
    asm volatile("cp.async.wait_group %0;" :: "n"(N));
}

// ---------------------------------------------------------------------------
// Block-wide sum of (a,b) pairs, 256 threads
// ---------------------------------------------------------------------------
__device__ __forceinline__ float2 blockReduce2(float a, float b) {
#pragma unroll
    for (int o = 16; o > 0; o >>= 1) {
        a += __shfl_down_sync(0xffffffffu, a, o);
        b += __shfl_down_sync(0xffffffffu, b, o);
    }
    __shared__ float2 sh[8];
    int lane = threadIdx.x & 31, wid = threadIdx.x >> 5;
    if (lane == 0) sh[wid] = make_float2(a, b);
    __syncthreads();
    if (wid == 0) {
        float2 v = (lane < 8) ? sh[lane] : make_float2(0.f, 0.f);
#pragma unroll
        for (int o = 4; o > 0; o >>= 1) {
            v.x += __shfl_down_sync(0xffffffffu, v.x, o);
            v.y += __shfl_down_sync(0xffffffffu, v.y, o);
        }
        if (lane == 0) sh[0] = v;
    }
    __syncthreads();
    return sh[0];
}

// ---------------------------------------------------------------------------
// Embedding + LayerNorm: one block per token
// ---------------------------------------------------------------------------
__global__ void embed_ln_kernel(const int* __restrict__ ids,
                                const float* __restrict__ wemb,
                                const float* __restrict__ pemb,
                                const float* __restrict__ semb,
                                const float* __restrict__ g,
                                const float* __restrict__ bta,
                                float* __restrict__ x) {
    int t = blockIdx.x;
    int s = t & (Sq - 1);
    int id = ids[t];
    float v[3];
    float sum = 0.f, sq = 0.f;
#pragma unroll
    for (int i = 0; i < 3; i++) {
        int d = threadIdx.x + i * 256;
        float val = wemb[(size_t)id * Dq + d] + pemb[(size_t)s * Dq + d] + semb[d];
        v[i] = val;
        sum += val;
        sq += val * val;
    }
    float2 r = blockReduce2(sum, sq);
    float mu = r.x * (1.0f / Dq);
    float var = r.y * (1.0f / Dq) - mu * mu;
    float rstd = rsqrtf(var + 1e-5f);
#pragma unroll
    for (int i = 0; i < 3; i++) {
        int d = threadIdx.x + i * 256;
        x[(size_t)t * Dq + d] = (v[i] - mu) * rstd * g[d] + bta[d];
    }
}

// ---------------------------------------------------------------------------
// out = LayerNorm(a + bvec) * g + beta : one block per token
// ---------------------------------------------------------------------------
__global__ void add_ln_kernel(const float* __restrict__ a,
                              const float* __restrict__ bvec,
                              const float* __restrict__ g,
                              const float* __restrict__ bta,
                              float* __restrict__ out) {
    int t = blockIdx.x;
    float v[3];
    float sum = 0.f, sq = 0.f;
#pragma unroll
    for (int i = 0; i < 3; i++) {
        int d = threadIdx.x + i * 256;
        float val = a[(size_t)t * Dq + d] + bvec[(size_t)t * Dq + d];
        v[i] = val;
        sum += val;
        sq += val * val;
    }
    float2 r = blockReduce2(sum, sq);
    float mu = r.x * (1.0f / Dq);
    float var = r.y * (1.0f / Dq) - mu * mu;
    float rstd = rsqrtf(var + 1e-5f);
#pragma unroll
    for (int i = 0; i < 3; i++) {
        int d = threadIdx.x + i * 256;
        out[(size_t)t * Dq + d] = (v[i] - mu) * rstd * g[d] + bta[d];
    }
}

// ---------------------------------------------------------------------------
// Elementwise RNE TF32 conversion (n multiple of 4)
// ---------------------------------------------------------------------------
__global__ void cvt_tf32_kernel(const float* __restrict__ in,
                                float* __restrict__ out, size_t n4) {
    size_t i = (size_t)blockIdx.x * 256 + threadIdx.x;
    if (i >= n4) return;
    float4 v = ((const float4*)in)[i];
    v.x = T32(v.x); v.y = T32(v.y); v.z = T32(v.z); v.w = T32(v.w);
    ((float4*)out)[i] = v;
}

// ---------------------------------------------------------------------------
// Pad + TF32-convert vocab weight [D,V] -> [D,Npad]; bias [V] -> [Npad]
// ---------------------------------------------------------------------------
__global__ void pad_vocab_kernel(const float* __restrict__ w,
                                 float* __restrict__ wp) {
    size_t gid = (size_t)blockIdx.x * 256 + threadIdx.x;
    size_t i4 = gid * 4;
    if (i4 >= (size_t)Dq * Npad) return;
    int k = (int)(i4 / Npad);
    int c = (int)(i4 % Npad);
    float4 v;
    v.x = (c + 0 < Vq) ? T32(w[(size_t)k * Vq + c + 0]) : 0.f;
    v.y = (c + 1 < Vq) ? T32(w[(size_t)k * Vq + c + 1]) : 0.f;
    v.z = (c + 2 < Vq) ? T32(w[(size_t)k * Vq + c + 2]) : 0.f;
    v.w = (c + 3 < Vq) ? T32(w[(size_t)k * Vq + c + 3]) : 0.f;
    *(float4*)(wp + i4) = v;
}

__global__ void pad_bias_kernel(const float* __restrict__ b,
                                float* __restrict__ bp) {
    int c = blockIdx.x * 256 + threadIdx.x;
    if (c < Npad) bp[c] = (c < Vq) ? b[c] : 0.f;
}

// ---------------------------------------------------------------------------
// TF32 WMMA GEMM, cp.async double-buffered: C[M,N] = A[M,K] @ B[K,N].
// A = fp32 activations (converted in-register after fragment load).
// B = pre-converted TF32 weights. 128x128 tile, BK=32, 8 warps.
// EPI: 0=none (direct store), 1=+bias, 2=+bias+exact GELU (smem-staged).
// Dynamic smem: 2-stage A [128][36] + 2-stage B [32][132] = 70656 B.
// ---------------------------------------------------------------------------
#define AS_LD 36
#define BS_LD 132
#define GEMM_SMEM_BYTES ((2 * 128 * AS_LD + 2 * 32 * BS_LD) * 4)

template <int EPI>
__device__ __forceinline__ void gemm_body(const float* __restrict__ A,
                                          const float* __restrict__ Bt,
                                          const float* __restrict__ bias,
                                          float* __restrict__ C,
                                          int N, int K, int ldB) {
    extern __shared__ float sm[];
    float* As = sm;                       // [2][128][AS_LD]
    float* Bs = sm + 2 * 128 * AS_LD;     // [2][32][BS_LD]
    uint32_t asb = (uint32_t)__cvta_generic_to_shared(As);
    uint32_t bsb = (uint32_t)__cvta_generic_to_shared(Bs);

    int tid = threadIdx.x;
    int row0 = blockIdx.y * 128, col0 = blockIdx.x * 128;
    int warp = tid >> 5, lane = tid & 31;
    int wm = warp & 3, wn = warp >> 2;

    wmma::fragment<wmma::accumulator, 16, 16, 8, float> acc[2][4];
#pragma unroll
    for (int i = 0; i < 2; i++)
#pragma unroll
        for (int j = 0; j < 4; j++)
            wmma::fill_fragment(acc[i][j], 0.0f);

    // cp.async issue of one k-slab into stage buf
    auto issue = [&](int k0, int buf) {
#pragma unroll
        for (int it = 0; it < 4; it++) {
            int idx = tid + it * 256;
            int r = idx >> 3, ck = (idx & 7) * 4;
            const float* src = A + (size_t)(row0 + r) * K + k0 + ck;
            cp16(asb + (uint32_t)(((buf * 128 + r) * AS_LD + ck) * 4), src);
        }
#pragma unroll
        for (int it = 0; it < 4; it++) {
            int idx = tid + it * 256;
            int r = idx >> 5, ck = (idx & 31) * 4;
            const float* src = Bt + (size_t)(k0 + r) * ldB + col0 + ck;
            cp16(bsb + (uint32_t)(((buf * 32 + r) * BS_LD + ck) * 4), src);
        }
        cp_commit();
    };

    int niter = K / 32;
    issue(0, 0);

    for (int i = 0; i < niter; i++) {
        if (i + 1 < niter) {
            issue((i + 1) * 32, (i + 1) & 1);
            cp_wait<1>();
        } else {
            cp_wait<0>();
        }
        __syncthreads();

        const float* as = As + (i & 1) * 128 * AS_LD;
        const float* bs = Bs + (i & 1) * 32 * BS_LD;
#pragma unroll
        for (int kk = 0; kk < 4; kk++) {
            wmma::fragment<wmma::matrix_a, 16, 16, 8, wmma::precision::tf32, wmma::row_major> af[2];
            wmma::fragment<wmma::matrix_b, 16, 16, 8, wmma::precision::tf32, wmma::row_major> bf[4];
#pragma unroll
            for (int ii = 0; ii < 2; ii++) {
                wmma::load_matrix_sync(af[ii], as + (wm * 32 + ii * 16) * AS_LD + kk * 8, AS_LD);
#pragma unroll
                for (int e = 0; e < af[ii].num_elements; e++)
                    af[ii].x[e] = T32(af[ii].x[e]);   // RNE, matches reference numerics
            }
#pragma unroll
            for (int j = 0; j < 4; j++)
                wmma::load_matrix_sync(bf[j], bs + (kk * 8) * BS_LD + wn * 64 + j * 16, BS_LD);
#pragma unroll
            for (int ii = 0; ii < 2; ii++)
#pragma unroll
                for (int j = 0; j < 4; j++)
                    wmma::mma_sync(acc[ii][j], af[ii], bf[j], acc[ii][j]);
        }
        __syncthreads();
    }

    if (EPI == 0) {
#pragma unroll
        for (int i = 0; i < 2; i++)
#pragma unroll
            for (int j = 0; j < 4; j++) {
                float* dst = C + (size_t)(row0 + wm * 32 + i * 16) * N
                               + col0 + wn * 64 + j * 16;
                wmma::store_matrix_sync(dst, acc[i][j], N, wmma::mem_row_major);
            }
    } else {
        // stage via smem (reuse As region; mainloop done, barrier passed)
        float* Cs = sm + warp * 320;  // [16][20] per warp
        int rr = lane >> 1, cc = (lane & 1) * 8;
#pragma unroll
        for (int i = 0; i < 2; i++) {
#pragma unroll
            for (int j = 0; j < 4; j++) {
                wmma::store_matrix_sync(Cs, acc[i][j], 20, wmma::mem_row_major);
                __syncwarp();
                int r = row0 + wm * 32 + i * 16 + rr;
                int c0l = col0 + wn * 64 + j * 16 + cc;
                float* dst = C + (size_t)r * N + c0l;
#pragma unroll
                for (int e = 0; e < 8; e++) {
                    int c = c0l + e;
                    if (c < N) {
                        float vv = Cs[rr * 20 + cc + e];
                        vv += bias[c];
                        if (EPI == 2) vv = 0.5f * vv * (1.0f + erff(vv * 0.70710678118654752f));
                        dst[e] = vv;
                    }
                }
                __syncwarp();
            }
        }
    }
}

template <int EPI>
__global__ void __launch_bounds__(256, 2)
gemm_tf32_kernel(const float* __restrict__ A, const float* __restrict__ Bt,
                 const float* __restrict__ bias, float* __restrict__ C,
                 int N, int K, int ldB) {
    gemm_body<EPI>(A, Bt, bias, C, N, K, ldB);
}

// Batched QKV: blockIdx.z selects weight + output (q/k/v contiguous in ws)
__global__ void __launch_bounds__(256, 2)
gemm_qkv_kernel(const float* __restrict__ A, const float* __restrict__ w0,
                const float* __restrict__ w1, const float* __restrict__ w2,
                float* __restrict__ c0) {
    const float* Bm = (blockIdx.z == 0) ? w0 : (blockIdx.z == 1) ? w1 : w2;
    float* C = c0 + (size_t)blockIdx.z * Tq * Dq;
    gemm_body<0>(A, Bm, nullptr, C, Dq, Dq, Dq);
}

// ---------------------------------------------------------------------------
// Attention scores (TF32 wmma): out[bh,q,k] = scale*dot(q,k), mask -> -inf
// ---------------------------------------------------------------------------
__global__ void __launch_bounds__(256)
attn_scores_tf32(const float* __restrict__ q, const float* __restrict__ k,
                 const int* __restrict__ mask, float* __restrict__ out) {
    __shared__ float Qs[64][68];
    __shared__ float Ks[64][68];
    __shared__ float Cs[8][16][20];
    int bh = blockIdx.z;
    int b = bh / Hq, h = bh % Hq;
    int q0 = blockIdx.y * 64, k0 = blockIdx.x * 64;
    int tid = threadIdx.x;

#pragma unroll
    for (int i = 0; i < 4; i++) {
        int idx = tid + i * 256;
        int r = idx >> 4;
        int c4 = (idx & 15) * 4;
        float4 qv = *(const float4*)(q + (size_t)(b * Sq + q0 + r) * Dq + h * HDq + c4);
        Qs[r][c4 + 0] = T32(qv.x); Qs[r][c4 + 1] = T32(qv.y);
        Qs[r][c4 + 2] = T32(qv.z); Qs[r][c4 + 3] = T32(qv.w);
        float4 kv = *(const float4*)(k + (size_t)(b * Sq + k0 + r) * Dq + h * HDq + c4);
        Ks[r][c4 + 0] = T32(kv.x); Ks[r][c4 + 1] = T32(kv.y);
        Ks[r][c4 + 2] = T32(kv.z); Ks[r][c4 + 3] = T32(kv.w);
    }
    __syncthreads();

    int warp = tid >> 5, lane = tid & 31;
    int wm = warp & 3, wn = warp >> 2;

    wmma::fragment<wmma::accumulator, 16, 16, 8, float> acc[2];
    wmma::fill_fragment(acc[0], 0.0f);
    wmma::fill_fragment(acc[1], 0.0f);

#pragma unroll
    for (int kk = 0; kk < 8; kk++) {
        wmma::fragment<wmma::matrix_a, 16, 16, 8, wmma::precision::tf32, wmma::row_major> af;
        wmma::load_matrix_sync(af, &Qs[wm * 16][kk * 8], 68);
#pragma unroll
        for (int j = 0; j < 2; j++) {
            wmma::fragment<wmma::matrix_b, 16, 16, 8, wmma::precision::tf32, wmma::col_major> bf;
            wmma::load_matrix_sync(bf, &Ks[wn * 32 + j * 16][kk * 8], 68);
            wmma::mma_sync(acc[j], af, bf, acc[j]);
        }
    }

    const float scale = 0.03608439182435161f;  // 1/sqrt(D=768)
    int rr = lane >> 1, cc = (lane & 1) * 8;
#pragma unroll
    for (int j = 0; j < 2; j++) {
        wmma::store_matrix_sync(&Cs[warp][0][0], acc[j], 20, wmma::mem_row_major);
        __syncwarp();
        int qr = q0 + wm * 16 + rr;
        int kc0 = k0 + wn * 32 + j * 16 + cc;
        float* dst = out + ((size_t)bh * Sq + qr) * Sq + kc0;
#pragma unroll
        for (int e = 0; e < 8; e++) {
            float vv = Cs[warp][rr][cc + e] * scale;
            if (mask[b * Sq + kc0 + e] == 0) vv = -INFINITY;
            dst[e] = vv;
        }
        __syncwarp();
    }
}

// ---------------------------------------------------------------------------
// In-place softmax over last dim (512). One warp per row.
// ---------------------------------------------------------------------------
__global__ void softmax_kernel(float* __restrict__ p) {
    int row = blockIdx.x * 4 + (threadIdx.x >> 5);
    int lane = threadIdx.x & 31;
    float* r = p + (size_t)row * Sq;
    float v[16];
    float m = -INFINITY;
#pragma unroll
    for (int i = 0; i < 16; i++) {
        v[i] = r[lane + i * 32];
        m = fmaxf(m, v[i]);
    }
#pragma unroll
    for (int o = 16; o > 0; o >>= 1) m = fmaxf(m, __shfl_xor_sync(0xffffffffu, m, o));
    float s = 0.f;
#pragma unroll
    for (int i = 0; i < 16; i++) {
        v[i] = __expf(v[i] - m);
        s += v[i];
    }
#pragma unroll
    for (int o = 16; o > 0; o >>= 1) s += __shfl_xor_sync(0xffffffffu, s, o);
    float inv = 1.0f / s;
#pragma unroll
    for (int i = 0; i < 16; i++) r[lane + i * 32] = v[i] * inv;
}

// ---------------------------------------------------------------------------
// o[b,q,h*64+d] = sum_k P[bh,q,k] * V[b,k,h*64+d]   (TF32 wmma)
// ---------------------------------------------------------------------------
__global__ void __launch_bounds__(256)
attn_av_tf32(const float* __restrict__ p, const float* __restrict__ v,
             float* __restrict__ o) {
    __shared__ float Ps[64][36];
    __shared__ float Vs[32][68];
    __shared__ float Cs[8][16][20];
    int bh = blockIdx.z;
    int b = bh / Hq, h = bh % Hq;
    int q0 = blockIdx.y * 64;
    int tid = threadIdx.x;
    int warp = tid >> 5, lane = tid & 31;
    int wm = warp & 3, wn = warp >> 2;

    wmma::fragment<wmma::accumulator, 16, 16, 8, float> acc[2];
    wmma::fill_fragment(acc[0], 0.0f);
    wmma::fill_fragment(acc[1], 0.0f);

    for (int k0 = 0; k0 < Sq; k0 += 32) {
#pragma unroll
        for (int i = 0; i < 2; i++) {
            int idx = tid + i * 256;
            int pr = idx >> 3, pc4 = (idx & 7) * 4;
            float4 pv = *(const float4*)(p + ((size_t)bh * Sq + q0 + pr) * Sq + k0 + pc4);
            Ps[pr][pc4 + 0] = T32(pv.x); Ps[pr][pc4 + 1] = T32(pv.y);
            Ps[pr][pc4 + 2] = T32(pv.z); Ps[pr][pc4 + 3] = T32(pv.w);
            int vr = idx >> 4, vc4 = (idx & 15) * 4;
            float4 vv = *(const float4*)(v + (size_t)(b * Sq + k0 + vr) * Dq + h * HDq + vc4);
            Vs[vr][vc4 + 0] = T32(vv.x); Vs[vr][vc4 + 1] = T32(vv.y);
            Vs[vr][vc4 + 2] = T32(vv.z); Vs[vr][vc4 + 3] = T32(vv.w);
        }
        __syncthreads();
#pragma unroll
        for (int kk = 0; kk < 4; kk++) {
            wmma::fragment<wmma::matrix_a, 16, 16, 8, wmma::precision::tf32, wmma::row_major> af;
            wmma::load_matrix_sync(af, &Ps[wm * 16][kk * 8], 36);
#pragma unroll
            for (int j = 0; j < 2; j++) {
                wmma::fragment<wmma::matrix_b, 16, 16, 8, wmma::precision::tf32, wmma::row_major> bf;
                wmma::load_matrix_sync(bf, &Vs[kk * 8][wn * 32 + j * 16], 68);
                wmma::mma_sync(acc[j], af, bf, acc[j]);
            }
        }
        __syncthreads();
    }

    int rr = lane >> 1, cc = (lane & 1) * 8;
#pragma unroll
    for (int j = 0; j < 2; j++) {
        wmma::store_matrix_sync(&Cs[warp][0][0], acc[j], 20, wmma::mem_row_major);
        __syncwarp();
        int qr = q0 + wm * 16 + rr;
        int dc = h * HDq + wn * 32 + j * 16 + cc;
        float* dst = o + (size_t)(b * Sq + qr) * Dq + dc;
#pragma unroll
        for (int e = 0; e < 8; e++) dst[e] = Cs[warp][rr][cc + e];
        __syncwarp();
    }
}

// ---------------------------------------------------------------------------
// Host orchestration (graph-capturable: kernel launches only)
// ---------------------------------------------------------------------------
extern "C" void kernel_launch(void* const* d_in, const int* in_sizes, int n_in,
                              void* d_out, int out_size) {
    const int*   ids  = (const int*)d_in[0];
    const int*   mask = (const int*)d_in[1];
    const float* wemb = (const float*)d_in[2];
    const float* pemb = (const float*)d_in[3];
    const float* semb = (const float*)d_in[4];
    const float* elng = (const float*)d_in[5];
    const float* elnb = (const float*)d_in[6];
    const float* Wq   = (const float*)d_in[7];
    const float* Wk   = (const float*)d_in[8];
    const float* Wv   = (const float*)d_in[9];
    const float* Wo   = (const float*)d_in[10];
    const float* f1w  = (const float*)d_in[11];
    const float* f1b  = (const float*)d_in[12];
    const float* f2w  = (const float*)d_in[13];
    const float* f2b  = (const float*)d_in[14];
    const float* l1g  = (const float*)d_in[15];
    const float* l1b  = (const float*)d_in[16];
    const float* l2g  = (const float*)d_in[17];
    const float* l2b  = (const float*)d_in[18];
    const float* outw = (const float*)d_in[19];
    const float* outb = (const float*)d_in[20];

    // opt into >48KB dynamic smem (idempotent; not a stream op)
    static bool attr_done = false;
    if (!attr_done) {
        cudaFuncSetAttribute(gemm_tf32_kernel<0>, cudaFuncAttributeMaxDynamicSharedMemorySize, GEMM_SMEM_BYTES);
        cudaFuncSetAttribute(gemm_tf32_kernel<1>, cudaFuncAttributeMaxDynamicSharedMemorySize, GEMM_SMEM_BYTES);
        cudaFuncSetAttribute(gemm_tf32_kernel<2>, cudaFuncAttributeMaxDynamicSharedMemorySize, GEMM_SMEM_BYTES);
        cudaFuncSetAttribute(gemm_qkv_kernel,     cudaFuncAttributeMaxDynamicSharedMemorySize, GEMM_SMEM_BYTES);
        attr_done = true;
    }

    float* ws = nullptr;
    cudaGetSymbolAddress((void**)&ws, g_ws);
    float* x  = ws;
    float* q  = ws + 1 * (size_t)Tq * Dq;
    float* kb = ws + 2 * (size_t)Tq * Dq;
    float* vb = ws + 3 * (size_t)Tq * Dq;
    float* tb = ws + 4 * (size_t)Tq * Dq;
    float* x1 = ws + 5 * (size_t)Tq * Dq;
    float* hb = ws + 6 * (size_t)Tq * Dq;
    float* wpad = hb + (size_t)Tq * Fq;
    float* bpad = wpad + (size_t)Dq * Npad;
    float* cWq = bpad + Npad;
    float* cWk = cWq + LDD;
    float* cWv = cWk + LDD;
    float* cWo = cWv + LDD;
    float* cF1 = cWo + LDD;
    float* cF2 = cF1 + LDF;

    float* logits = (float*)d_out;                       // [B*S, V]
    float* attn   = logits + (size_t)Tq * Vq;            // [L, B*H, S, S]

    // ---- pre-convert weights to TF32 (RNE) + pad vocab ----
    {
        size_t n4dd = LDD / 4;
        unsigned gdd = (unsigned)((n4dd + 255) / 256);
        cvt_tf32_kernel<<<gdd, 256>>>(Wq, cWq, n4dd);
        cvt_tf32_kernel<<<gdd, 256>>>(Wk, cWk, n4dd);
        cvt_tf32_kernel<<<gdd, 256>>>(Wv, cWv, n4dd);
        cvt_tf32_kernel<<<gdd, 256>>>(Wo, cWo, n4dd);
        size_t n4df = LDF / 4;
        unsigned gdf = (unsigned)((n4df + 255) / 256);
        cvt_tf32_kernel<<<gdf, 256>>>(f1w, cF1, n4df);
        cvt_tf32_kernel<<<gdf, 256>>>(f2w, cF2, n4df);
        size_t n4v = ((size_t)Dq * Npad) / 4;
        pad_vocab_kernel<<<(unsigned)((n4v + 255) / 256), 256>>>(outw, wpad);
        pad_bias_kernel<<<(Npad + 255) / 256, 256>>>(outb, bpad);
    }

    embed_ln_kernel<<<Tq, 256>>>(ids, wemb, pemb, semb, elng, elnb, x);

    for (int l = 0; l < Lq; l++) {
        float* slab = attn + (size_t)l * Bq * Hq * Sq * Sq;
        dim3 gDD(Dq / 128, Tq / 128);  // (6,16)

        gemm_qkv_kernel<<<dim3(Dq / 128, Tq / 128, 3), 256, GEMM_SMEM_BYTES>>>(
            x, cWq + (size_t)l * Dq * Dq, cWk + (size_t)l * Dq * Dq,
            cWv + (size_t)l * Dq * Dq, q);

        attn_scores_tf32<<<dim3(Sq / 64, Sq / 64, Bq * Hq), 256>>>(q, kb, mask, slab);
        softmax_kernel<<<Bq * Hq * Sq / 4, 128>>>(slab);
        attn_av_tf32<<<dim3(1, Sq / 64, Bq * Hq), 256>>>(slab, vb, tb);

        gemm_tf32_kernel<0><<<gDD, 256, GEMM_SMEM_BYTES>>>(
            tb, cWo + (size_t)l * Dq * Dq, nullptr, q, Dq, Dq, Dq);
        add_ln_kernel<<<Tq, 256>>>(x, q, l1g + (size_t)l * Dq, l1b + (size_t)l * Dq, x1);

        gemm_tf32_kernel<2><<<dim3(Fq / 128, Tq / 128), 256, GEMM_SMEM_BYTES>>>(
            x1, cF1 + (size_t)l * Dq * Fq, f1b + (size_t)l * Fq, hb, Fq, Dq, Fq);
        gemm_tf32_kernel<1><<<dim3(Dq / 128, Tq / 128), 256, GEMM_SMEM_BYTES>>>(
            hb, cF2 + (size_t)l * Fq * Dq, f2b + (size_t)l * Dq, tb, Dq, Fq, Dq);
        add_ln_kernel<<<Tq, 256>>>(x1, tb, l2g + (size_t)l * Dq, l2b + (size_t)l * Dq, x);
    }

    gemm_tf32_kernel<1><<<dim3(Npad / 128, Tq / 128), 256, GEMM_SMEM_BYTES>>>(
        x, wpad, bpad, logits, Vq, Dq, Npad);
}

// round 10
// speedup vs baseline: 1.1871x; 1.0014x over previous
#include <cuda_runtime.h>
#include <mma.h>
#include <math.h>
#include <cstdint>

using namespace nvcuda;

// BERT-base forward: B=4, S=512, L=12, D=768, H=12, F=3072, V=30522
#define Bq 4
#define Sq 512
#define Lq 12
#define Dq 768
#define Hq 12
#define Fq 3072
#define Vq 30522
#define HDq 64
#define Tq 2048    // B*S tokens
#define Npad 30592 // 239*128, padded vocab width

#define LDD ((size_t)Lq * Dq * Dq)
#define LDF ((size_t)Lq * Dq * Fq)

// Workspace: activations + padded vocab + TF32-preconverted weights
// x,q,kb,vb,tb,x1 [T,D]; hb [T,F]; wpad [D,Npad]; bpad [Npad];
// cWq,cWk,cWv,cWo [L,D,D]; cF1 [L,D,F]; cF2 [L,F,D]
__device__ float g_ws[6 * (size_t)Tq * Dq + (size_t)Tq * Fq
                      + (size_t)Dq * Npad + Npad
                      + 4 * LDD + 2 * LDF];

__device__ __forceinline__ float T32(float x) { return wmma::__float_to_tf32(x); }

__device__ __forceinline__ void cp16(uint32_t dst, const float* src) {
    asm volatile("cp.async.cg.shared.global [%0], [%1], 16;" :: "r"(dst), "l"(src));
}
__device__ __forceinline__ void cp_commit() {
    asm volatile("cp.async.commit_group;");
}
template <int N>
__device__ __forceinline__ void cp_wait() {
    asm volatile("cp.async.wait_group %0;" :: "n"(N));
}

// ---------------------------------------------------------------------------
// Block-wide sum of (a,b) pairs, 256 threads
// ---------------------------------------------------------------------------
__device__ __forceinline__ float2 blockReduce2(float a, float b) {
#pragma unroll
    for (int o = 16; o > 0; o >>= 1) {
        a += __shfl_down_sync(0xffffffffu, a, o);
        b += __shfl_down_sync(0xffffffffu, b, o);
    }
    __shared__ float2 sh[8];
    int lane = threadIdx.x & 31, wid = threadIdx.x >> 5;
    if (lane == 0) sh[wid] = make_float2(a, b);
    __syncthreads();
    if (wid == 0) {
        float2 v = (lane < 8) ? sh[lane] : make_float2(0.f, 0.f);
#pragma unroll
        for (int o = 4; o > 0; o >>= 1) {
            v.x += __shfl_down_sync(0xffffffffu, v.x, o);
            v.y += __shfl_down_sync(0xffffffffu, v.y, o);
        }
        if (lane == 0) sh[0] = v;
    }
    __syncthreads();
    return sh[0];
}

// ---------------------------------------------------------------------------
// Embedding + LayerNorm: one block per token
// ---------------------------------------------------------------------------
__global__ void embed_ln_kernel(const int* __restrict__ ids,
                                const float* __restrict__ wemb,
                                const float* __restrict__ pemb,
                                const float* __restrict__ semb,
                                const float* __restrict__ g,
                                const float* __restrict__ bta,
                                float* __restrict__ x) {
    int t = blockIdx.x;
    int s = t & (Sq - 1);
    int id = ids[t];
    float v[3];
    float sum = 0.f, sq = 0.f;
#pragma unroll
    for (int i = 0; i < 3; i++) {
        int d = threadIdx.x + i * 256;
        float val = wemb[(size_t)id * Dq + d] + pemb[(size_t)s * Dq + d] + semb[d];
        v[i] = val;
        sum += val;
        sq += val * val;
    }
    float2 r = blockReduce2(sum, sq);
    float mu = r.x * (1.0f / Dq);
    float var = r.y * (1.0f / Dq) - mu * mu;
    float rstd = rsqrtf(var + 1e-5f);
#pragma unroll
    for (int i = 0; i < 3; i++) {
        int d = threadIdx.x + i * 256;
        x[(size_t)t * Dq + d] = (v[i] - mu) * rstd * g[d] + bta[d];
    }
}

// ---------------------------------------------------------------------------
// out = LayerNorm(a + bvec) * g + beta : one block per token
// ---------------------------------------------------------------------------
__global__ void add_ln_kernel(const float* __restrict__ a,
                              const float* __restrict__ bvec,
                              const float* __restrict__ g,
                              const float* __restrict__ bta,
                              float* __restrict__ out) {
    int t = blockIdx.x;
    float v[3];
    float sum = 0.f, sq = 0.f;
#pragma unroll
    for (int i = 0; i < 3; i++) {
        int d = threadIdx.x + i * 256;
        float val = a[(size_t)t * Dq + d] + bvec[(size_t)t * Dq + d];
        v[i] = val;
        sum += val;
        sq += val * val;
    }
    float2 r = blockReduce2(sum, sq);
    float mu = r.x * (1.0f / Dq);
    float var = r.y * (1.0f / Dq) - mu * mu;
    float rstd = rsqrtf(var + 1e-5f);
#pragma unroll
    for (int i = 0; i < 3; i++) {
        int d = threadIdx.x + i * 256;
        out[(size_t)t * Dq + d] = (v[i] - mu) * rstd * g[d] + bta[d];
    }
}

// ---------------------------------------------------------------------------
// Elementwise RNE TF32 conversion (n multiple of 4)
// ---------------------------------------------------------------------------
__global__ void cvt_tf32_kernel(const float* __restrict__ in,
                                float* __restrict__ out, size_t n4) {
    size_t i = (size_t)blockIdx.x * 256 + threadIdx.x;
    if (i >= n4) return;
    float4 v = ((const float4*)in)[i];
    v.x = T32(v.x); v.y = T32(v.y); v.z = T32(v.z); v.w = T32(v.w);
    ((float4*)out)[i] = v;
}

// ---------------------------------------------------------------------------
// Pad + TF32-convert vocab weight [D,V] -> [D,Npad]; bias [V] -> [Npad]
// ---------------------------------------------------------------------------
__global__ void pad_vocab_kernel(const float* __restrict__ w,
                                 float* __restrict__ wp) {
    size_t gid = (size_t)blockIdx.x * 256 + threadIdx.x;
    size_t i4 = gid * 4;
    if (i4 >= (size_t)Dq * Npad) return;
    int k = (int)(i4 / Npad);
    int c = (int)(i4 % Npad);
    float4 v;
    v.x = (c + 0 < Vq) ? T32(w[(size_t)k * Vq + c + 0]) : 0.f;
    v.y = (c + 1 < Vq) ? T32(w[(size_t)k * Vq + c + 1]) : 0.f;
    v.z = (c + 2 < Vq) ? T32(w[(size_t)k * Vq + c + 2]) : 0.f;
    v.w = (c + 3 < Vq) ? T32(w[(size_t)k * Vq + c + 3]) : 0.f;
    *(float4*)(wp + i4) = v;
}

__global__ void pad_bias_kernel(const float* __restrict__ b,
                                float* __restrict__ bp) {
    int c = blockIdx.x * 256 + threadIdx.x;
    if (c < Npad) bp[c] = (c < Vq) ? b[c] : 0.f;
}

// ---------------------------------------------------------------------------
// TF32 WMMA GEMM, cp.async double-buffered: C[M,N] = A[M,K] @ B[K,N].
// A = fp32 activations (converted in-register after fragment load).
// B = pre-converted TF32 weights. 128x128 tile, BK=32, 8 warps.
// EPI: 0=none (direct store), 1=+bias, 2=+bias+exact GELU (smem-staged).
// Dynamic smem: 2-stage A [128][36] + 2-stage B [32][132] = 70656 B.
// ---------------------------------------------------------------------------
#define AS_LD 36
#define BS_LD 132
#define GEMM_SMEM_BYTES ((2 * 128 * AS_LD + 2 * 32 * BS_LD) * 4)

template <int EPI>
__device__ __forceinline__ void gemm_body(const float* __restrict__ A,
                                          const float* __restrict__ Bt,
                                          const float* __restrict__ bias,
                                          float* __restrict__ C,
                                          int N, int K, int ldB) {
    extern __shared__ float sm[];
    float* As = sm;                       // [2][128][AS_LD]
    float* Bs = sm + 2 * 128 * AS_LD;     // [2][32][BS_LD]
    uint32_t asb = (uint32_t)__cvta_generic_to_shared(As);
    uint32_t bsb = (uint32_t)__cvta_generic_to_shared(Bs);

    int tid = threadIdx.x;
    int row0 = blockIdx.y * 128, col0 = blockIdx.x * 128;
    int warp = tid >> 5, lane = tid & 31;
    int wm = warp & 3, wn = warp >> 2;

    wmma::fragment<wmma::accumulator, 16, 16, 8, float> acc[2][4];
#pragma unroll
    for (int i = 0; i < 2; i++)
#pragma unroll
        for (int j = 0; j < 4; j++)
            wmma::fill_fragment(acc[i][j], 0.0f);

    // cp.async issue of one k-slab into stage buf
    auto issue = [&](int k0, int buf) {
#pragma unroll
        for (int it = 0; it < 4; it++) {
            int idx = tid + it * 256;
            int r = idx >> 3, ck = (idx & 7) * 4;
            const float* src = A + (size_t)(row0 + r) * K + k0 + ck;
            cp16(asb + (uint32_t)(((buf * 128 + r) * AS_LD + ck) * 4), src);
        }
#pragma unroll
        for (int it = 0; it < 4; it++) {
            int idx = tid + it * 256;
            int r = idx >> 5, ck = (idx & 31) * 4;
            const float* src = Bt + (size_t)(k0 + r) * ldB + col0 + ck;
            cp16(bsb + (uint32_t)(((buf * 32 + r) * BS_LD + ck) * 4), src);
        }
        cp_commit();
    };

    int niter = K / 32;
    issue(0, 0);

    for (int i = 0; i < niter; i++) {
        if (i + 1 < niter) {
            issue((i + 1) * 32, (i + 1) & 1);
            cp_wait<1>();
        } else {
            cp_wait<0>();
        }
        __syncthreads();

        const float* as = As + (i & 1) * 128 * AS_LD;
        const float* bs = Bs + (i & 1) * 32 * BS_LD;
#pragma unroll
        for (int kk = 0; kk < 4; kk++) {
            wmma::fragment<wmma::matrix_a, 16, 16, 8, wmma::precision::tf32, wmma::row_major> af[2];
            wmma::fragment<wmma::matrix_b, 16, 16, 8, wmma::precision::tf32, wmma::row_major> bf[4];
#pragma unroll
            for (int ii = 0; ii < 2; ii++) {
                wmma::load_matrix_sync(af[ii], as + (wm * 32 + ii * 16) * AS_LD + kk * 8, AS_LD);
#pragma unroll
                for (int e = 0; e < af[ii].num_elements; e++)
                    af[ii].x[e] = T32(af[ii].x[e]);   // RNE, matches reference numerics
            }
#pragma unroll
            for (int j = 0; j < 4; j++)
                wmma::load_matrix_sync(bf[j], bs + (kk * 8) * BS_LD + wn * 64 + j * 16, BS_LD);
#pragma unroll
            for (int ii = 0; ii < 2; ii++)
#pragma unroll
                for (int j = 0; j < 4; j++)
                    wmma::mma_sync(acc[ii][j], af[ii], bf[j], acc[ii][j]);
        }
        __syncthreads();
    }

    if (EPI == 0) {
#pragma unroll
        for (int i = 0; i < 2; i++)
#pragma unroll
            for (int j = 0; j < 4; j++) {
                float* dst = C + (size_t)(row0 + wm * 32 + i * 16) * N
                               + col0 + wn * 64 + j * 16;
                wmma::store_matrix_sync(dst, acc[i][j], N, wmma::mem_row_major);
            }
    } else {
        // stage via smem (reuse As region; mainloop done, barrier passed)
        float* Cs = sm + warp * 320;  // [16][20] per warp
        int rr = lane >> 1, cc = (lane & 1) * 8;
#pragma unroll
        for (int i = 0; i < 2; i++) {
#pragma unroll
            for (int j = 0; j < 4; j++) {
                wmma::store_matrix_sync(Cs, acc[i][j], 20, wmma::mem_row_major);
                __syncwarp();
                int r = row0 + wm * 32 + i * 16 + rr;
                int c0l = col0 + wn * 64 + j * 16 + cc;
                float* dst = C + (size_t)r * N + c0l;
#pragma unroll
                for (int e = 0; e < 8; e++) {
                    int c = c0l + e;
                    if (c < N) {
                        float vv = Cs[rr * 20 + cc + e];
                        vv += bias[c];
                        if (EPI == 2) vv = 0.5f * vv * (1.0f + erff(vv * 0.70710678118654752f));
                        dst[e] = vv;
                    }
                }
                __syncwarp();
            }
        }
    }
}

template <int EPI>
__global__ void __launch_bounds__(256, 2)
gemm_tf32_kernel(const float* __restrict__ A, const float* __restrict__ Bt,
                 const float* __restrict__ bias, float* __restrict__ C,
                 int N, int K, int ldB) {
    gemm_body<EPI>(A, Bt, bias, C, N, K, ldB);
}

// Batched QKV: blockIdx.z selects weight + output (q/k/v contiguous in ws)
__global__ void __launch_bounds__(256, 2)
gemm_qkv_kernel(const float* __restrict__ A, const float* __restrict__ w0,
                const float* __restrict__ w1, const float* __restrict__ w2,
                float* __restrict__ c0) {
    const float* Bm = (blockIdx.z == 0) ? w0 : (blockIdx.z == 1) ? w1 : w2;
    float* C = c0 + (size_t)blockIdx.z * Tq * Dq;
    gemm_body<0>(A, Bm, nullptr, C, Dq, Dq, Dq);
}

// ---------------------------------------------------------------------------
// Attention scores (TF32 wmma): out[bh,q,k] = scale*dot(q,k), mask -> -inf
// ---------------------------------------------------------------------------
__global__ void __launch_bounds__(256)
attn_scores_tf32(const float* __restrict__ q, const float* __restrict__ k,
                 const int* __restrict__ mask, float* __restrict__ out) {
    __shared__ float Qs[64][68];
    __shared__ float Ks[64][68];
    __shared__ float Cs[8][16][20];
    int bh = blockIdx.z;
    int b = bh / Hq, h = bh % Hq;
    int q0 = blockIdx.y * 64, k0 = blockIdx.x * 64;
    int tid = threadIdx.x;

#pragma unroll
    for (int i = 0; i < 4; i++) {
        int idx = tid + i * 256;
        int r = idx >> 4;
        int c4 = (idx & 15) * 4;
        float4 qv = *(const float4*)(q + (size_t)(b * Sq + q0 + r) * Dq + h * HDq + c4);
        Qs[r][c4 + 0] = T32(qv.x); Qs[r][c4 + 1] = T32(qv.y);
        Qs[r][c4 + 2] = T32(qv.z); Qs[r][c4 + 3] = T32(qv.w);
        float4 kv = *(const float4*)(k + (size_t)(b * Sq + k0 + r) * Dq + h * HDq + c4);
        Ks[r][c4 + 0] = T32(kv.x); Ks[r][c4 + 1] = T32(kv.y);
        Ks[r][c4 + 2] = T32(kv.z); Ks[r][c4 + 3] = T32(kv.w);
    }
    __syncthreads();

    int warp = tid >> 5, lane = tid & 31;
    int wm = warp & 3, wn = warp >> 2;

    wmma::fragment<wmma::accumulator, 16, 16, 8, float> acc[2];
    wmma::fill_fragment(acc[0], 0.0f);
    wmma::fill_fragment(acc[1], 0.0f);

#pragma unroll
    for (int kk = 0; kk < 8; kk++) {
        wmma::fragment<wmma::matrix_a, 16, 16, 8, wmma::precision::tf32, wmma::row_major> af;
        wmma::load_matrix_sync(af, &Qs[wm * 16][kk * 8], 68);
#pragma unroll
        for (int j = 0; j < 2; j++) {
            wmma::fragment<wmma::matrix_b, 16, 16, 8, wmma::precision::tf32, wmma::col_major> bf;
            wmma::load_matrix_sync(bf, &Ks[wn * 32 + j * 16][kk * 8], 68);
            wmma::mma_sync(acc[j], af, bf, acc[j]);
        }
    }

    const float scale = 0.03608439182435161f;  // 1/sqrt(D=768)
    int rr = lane >> 1, cc = (lane & 1) * 8;
#pragma unroll
    for (int j = 0; j < 2; j++) {
        wmma::store_matrix_sync(&Cs[warp][0][0], acc[j], 20, wmma::mem_row_major);
        __syncwarp();
        int qr = q0 + wm * 16 + rr;
        int kc0 = k0 + wn * 32 + j * 16 + cc;
        float* dst = out + ((size_t)bh * Sq + qr) * Sq + kc0;
#pragma unroll
        for (int e = 0; e < 8; e++) {
            float vv = Cs[warp][rr][cc + e] * scale;
            if (mask[b * Sq + kc0 + e] == 0) vv = -INFINITY;
            dst[e] = vv;
        }
        __syncwarp();
    }
}

// ---------------------------------------------------------------------------
// In-place softmax over last dim (512). One warp per row.
// ---------------------------------------------------------------------------
__global__ void softmax_kernel(float* __restrict__ p) {
    int row = blockIdx.x * 4 + (threadIdx.x >> 5);
    int lane = threadIdx.x & 31;
    float* r = p + (size_t)row * Sq;
    float v[16];
    float m = -INFINITY;
#pragma unroll
    for (int i = 0; i < 16; i++) {
        v[i] = r[lane + i * 32];
        m = fmaxf(m, v[i]);
    }
#pragma unroll
    for (int o = 16; o > 0; o >>= 1) m = fmaxf(m, __shfl_xor_sync(0xffffffffu, m, o));
    float s = 0.f;
#pragma unroll
    for (int i = 0; i < 16; i++) {
        v[i] = __expf(v[i] - m);
        s += v[i];
    }
#pragma unroll
    for (int o = 16; o > 0; o >>= 1) s += __shfl_xor_sync(0xffffffffu, s, o);
    float inv = 1.0f / s;
#pragma unroll
    for (int i = 0; i < 16; i++) r[lane + i * 32] = v[i] * inv;
}

// ---------------------------------------------------------------------------
// o[b,q,h*64+d] = sum_k P[bh,q,k] * V[b,k,h*64+d]   (TF32 wmma)
// ---------------------------------------------------------------------------
__global__ void __launch_bounds__(256)
attn_av_tf32(const float* __restrict__ p, const float* __restrict__ v,
             float* __restrict__ o) {
    __shared__ float Ps[64][36];
    __shared__ float Vs[32][68];
    __shared__ float Cs[8][16][20];
    int bh = blockIdx.z;
    int b = bh / Hq, h = bh % Hq;
    int q0 = blockIdx.y * 64;
    int tid = threadIdx.x;
    int warp = tid >> 5, lane = tid & 31;
    int wm = warp & 3, wn = warp >> 2;

    wmma::fragment<wmma::accumulator, 16, 16, 8, float> acc[2];
    wmma::fill_fragment(acc[0], 0.0f);
    wmma::fill_fragment(acc[1], 0.0f);

    for (int k0 = 0; k0 < Sq; k0 += 32) {
#pragma unroll
        for (int i = 0; i < 2; i++) {
            int idx = tid + i * 256;
            int pr = idx >> 3, pc4 = (idx & 7) * 4;
            float4 pv = *(const float4*)(p + ((size_t)bh * Sq + q0 + pr) * Sq + k0 + pc4);
            Ps[pr][pc4 + 0] = T32(pv.x); Ps[pr][pc4 + 1] = T32(pv.y);
            Ps[pr][pc4 + 2] = T32(pv.z); Ps[pr][pc4 + 3] = T32(pv.w);
            int vr = idx >> 4, vc4 = (idx & 15) * 4;
            float4 vv = *(const float4*)(v + (size_t)(b * Sq + k0 + vr) * Dq + h * HDq + vc4);
            Vs[vr][vc4 + 0] = T32(vv.x); Vs[vr][vc4 + 1] = T32(vv.y);
            Vs[vr][vc4 + 2] = T32(vv.z); Vs[vr][vc4 + 3] = T32(vv.w);
        }
        __syncthreads();
#pragma unroll
        for (int kk = 0; kk < 4; kk++) {
            wmma::fragment<wmma::matrix_a, 16, 16, 8, wmma::precision::tf32, wmma::row_major> af;
            wmma::load_matrix_sync(af, &Ps[wm * 16][kk * 8], 36);
#pragma unroll
            for (int j = 0; j < 2; j++) {
                wmma::fragment<wmma::matrix_b, 16, 16, 8, wmma::precision::tf32, wmma::row_major> bf;
                wmma::load_matrix_sync(bf, &Vs[kk * 8][wn * 32 + j * 16], 68);
                wmma::mma_sync(acc[j], af, bf, acc[j]);
            }
        }
        __syncthreads();
    }

    int rr = lane >> 1, cc = (lane & 1) * 8;
#pragma unroll
    for (int j = 0; j < 2; j++) {
        wmma::store_matrix_sync(&Cs[warp][0][0], acc[j], 20, wmma::mem_row_major);
        __syncwarp();
        int qr = q0 + wm * 16 + rr;
        int dc = h * HDq + wn * 32 + j * 16 + cc;
        float* dst = o + (size_t)(b * Sq + qr) * Dq + dc;
#pragma unroll
        for (int e = 0; e < 8; e++) dst[e] = Cs[warp][rr][cc + e];
        __syncwarp();
    }
}

// ---------------------------------------------------------------------------
// Host orchestration (graph-capturable: kernel launches only)
// ---------------------------------------------------------------------------
extern "C" void kernel_launch(void* const* d_in, const int* in_sizes, int n_in,
                              void* d_out, int out_size) {
    const int*   ids  = (const int*)d_in[0];
    const int*   mask = (const int*)d_in[1];
    const float* wemb = (const float*)d_in[2];
    const float* pemb = (const float*)d_in[3];
    const float* semb = (const float*)d_in[4];
    const float* elng = (const float*)d_in[5];
    const float* elnb = (const float*)d_in[6];
    const float* Wq   = (const float*)d_in[7];
    const float* Wk   = (const float*)d_in[8];
    const float* Wv   = (const float*)d_in[9];
    const float* Wo   = (const float*)d_in[10];
    const float* f1w  = (const float*)d_in[11];
    const float* f1b  = (const float*)d_in[12];
    const float* f2w  = (const float*)d_in[13];
    const float* f2b  = (const float*)d_in[14];
    const float* l1g  = (const float*)d_in[15];
    const float* l1b  = (const float*)d_in[16];
    const float* l2g  = (const float*)d_in[17];
    const float* l2b  = (const float*)d_in[18];
    const float* outw = (const float*)d_in[19];
    const float* outb = (const float*)d_in[20];

    // opt into >48KB dynamic smem (idempotent; not a stream op)
    static bool attr_done = false;
    if (!attr_done) {
        cudaFuncSetAttribute(gemm_tf32_kernel<0>, cudaFuncAttributeMaxDynamicSharedMemorySize, GEMM_SMEM_BYTES);
        cudaFuncSetAttribute(gemm_tf32_kernel<1>, cudaFuncAttributeMaxDynamicSharedMemorySize, GEMM_SMEM_BYTES);
        cudaFuncSetAttribute(gemm_tf32_kernel<2>, cudaFuncAttributeMaxDynamicSharedMemorySize, GEMM_SMEM_BYTES);
        cudaFuncSetAttribute(gemm_qkv_kernel,     cudaFuncAttributeMaxDynamicSharedMemorySize, GEMM_SMEM_BYTES);
        attr_done = true;
    }

    float* ws = nullptr;
    cudaGetSymbolAddress((void**)&ws, g_ws);
    float* x  = ws;
    float* q  = ws + 1 * (size_t)Tq * Dq;
    float* kb = ws + 2 * (size_t)Tq * Dq;
    float* vb = ws + 3 * (size_t)Tq * Dq;
    float* tb = ws + 4 * (size_t)Tq * Dq;
    float* x1 = ws + 5 * (size_t)Tq * Dq;
    float* hb = ws + 6 * (size_t)Tq * Dq;
    float* wpad = hb + (size_t)Tq * Fq;
    float* bpad = wpad + (size_t)Dq * Npad;
    float* cWq = bpad + Npad;
    float* cWk = cWq + LDD;
    float* cWv = cWk + LDD;
    float* cWo = cWv + LDD;
    float* cF1 = cWo + LDD;
    float* cF2 = cF1 + LDF;

    float* logits = (float*)d_out;                       // [B*S, V]
    float* attn   = logits + (size_t)Tq * Vq;            // [L, B*H, S, S]

    // ---- pre-convert weights to TF32 (RNE) + pad vocab ----
    {
        size_t n4dd = LDD / 4;
        unsigned gdd = (unsigned)((n4dd + 255) / 256);
        cvt_tf32_kernel<<<gdd, 256>>>(Wq, cWq, n4dd);
        cvt_tf32_kernel<<<gdd, 256>>>(Wk, cWk, n4dd);
        cvt_tf32_kernel<<<gdd, 256>>>(Wv, cWv, n4dd);
        cvt_tf32_kernel<<<gdd, 256>>>(Wo, cWo, n4dd);
        size_t n4df = LDF / 4;
        unsigned gdf = (unsigned)((n4df + 255) / 256);
        cvt_tf32_kernel<<<gdf, 256>>>(f1w, cF1, n4df);
        cvt_tf32_kernel<<<gdf, 256>>>(f2w, cF2, n4df);
        size_t n4v = ((size_t)Dq * Npad) / 4;
        pad_vocab_kernel<<<(unsigned)((n4v + 255) / 256), 256>>>(outw, wpad);
        pad_bias_kernel<<<(Npad + 255) / 256, 256>>>(outb, bpad);
    }

    embed_ln_kernel<<<Tq, 256>>>(ids, wemb, pemb, semb, elng, elnb, x);

    for (int l = 0; l < Lq; l++) {
        float* slab = attn + (size_t)l * Bq * Hq * Sq * Sq;
        dim3 gDD(Dq / 128, Tq / 128);  // (6,16)

        gemm_qkv_kernel<<<dim3(Dq / 128, Tq / 128, 3), 256, GEMM_SMEM_BYTES>>>(
            x, cWq + (size_t)l * Dq * Dq, cWk + (size_t)l * Dq * Dq,
            cWv + (size_t)l * Dq * Dq, q);

        attn_scores_tf32<<<dim3(Sq / 64, Sq / 64, Bq * Hq), 256>>>(q, kb, mask, slab);
        softmax_kernel<<<Bq * Hq * Sq / 4, 128>>>(slab);
        attn_av_tf32<<<dim3(1, Sq / 64, Bq * Hq), 256>>>(slab, vb, tb);

        gemm_tf32_kernel<0><<<gDD, 256, GEMM_SMEM_BYTES>>>(
            tb, cWo + (size_t)l * Dq * Dq, nullptr, q, Dq, Dq, Dq);
        add_ln_kernel<<<Tq, 256>>>(x, q, l1g + (size_t)l * Dq, l1b + (size_t)l * Dq, x1);

        gemm_tf32_kernel<2><<<dim3(Fq / 128, Tq / 128), 256, GEMM_SMEM_BYTES>>>(
            x1, cF1 + (size_t)l * Dq * Fq, f1b + (size_t)l * Fq, hb, Fq, Dq, Fq);
        gemm_tf32_kernel<1><<<dim3(Dq / 128, Tq / 128), 256, GEMM_SMEM_BYTES>>>(
            hb, cF2 + (size_t)l * Fq * Dq, f2b + (size_t)l * Dq, tb, Dq, Fq, Dq);
        add_ln_kernel<<<Tq, 256>>>(x1, tb, l2g + (size_t)l * Dq, l2b + (size_t)l * Dq, x);
    }

    gemm_tf32_kernel<1><<<dim3(Npad / 128, Tq / 128), 256, GEMM_SMEM_BYTES>>>(
        x, wpad, bpad, logits, Vq, Dq, Npad);
}

// round 12
// speedup vs baseline: 1.2435x; 1.0475x over previous
#include <cuda_runtime.h>
#include <mma.h>
#include <math.h>
#include <cstdint>

using namespace nvcuda;

// BERT-base forward: B=4, S=512, L=12, D=768, H=12, F=3072, V=30522
#define Bq 4
#define Sq 512
#define Lq 12
#define Dq 768
#define Hq 12
#define Fq 3072
#define Vq 30522
#define HDq 64
#define Tq 2048    // B*S tokens
#define Npad 30592 // 239*128, padded vocab width

#define LDD ((size_t)Lq * Dq * Dq)
#define LDF ((size_t)Lq * Dq * Fq)

// Workspace: x,xT,x1,x1T,q,kb,vb,tb [T,D]; hb [T,F]; wpad [D,Npad]; bpad;
// cWq,cWk,cWv,cWo [L,D,D]; cF1 [L,D,F]; cF2 [L,F,D]  (tf32-rounded weights)
__device__ float g_ws[8 * (size_t)Tq * Dq + (size_t)Tq * Fq
                      + (size_t)Dq * Npad + Npad
                      + 4 * LDD + 2 * LDF];

__device__ __forceinline__ float T32(float x) { return wmma::__float_to_tf32(x); }

__device__ __forceinline__ void cp16(uint32_t dst, const float* src) {
    asm volatile("cp.async.cg.shared.global [%0], [%1], 16;" :: "r"(dst), "l"(src));
}
__device__ __forceinline__ void cp_commit() {
    asm volatile("cp.async.commit_group;");
}
template <int N>
__device__ __forceinline__ void cp_wait() {
    asm volatile("cp.async.wait_group %0;" :: "n"(N));
}
__device__ __forceinline__ uint32_t smem_u32(const void* p) {
    return (uint32_t)__cvta_generic_to_shared(p);
}

// ---------------------------------------------------------------------------
// Block-wide sum of (a,b) pairs, 256 threads
// ---------------------------------------------------------------------------
__device__ __forceinline__ float2 blockReduce2(float a, float b) {
#pragma unroll
    for (int o = 16; o > 0; o >>= 1) {
        a += __shfl_down_sync(0xffffffffu, a, o);
        b += __shfl_down_sync(0xffffffffu, b, o);
    }
    __shared__ float2 sh[8];
    int lane = threadIdx.x & 31, wid = threadIdx.x >> 5;
    if (lane == 0) sh[wid] = make_float2(a, b);
    __syncthreads();
    if (wid == 0) {
        float2 v = (lane < 8) ? sh[lane] : make_float2(0.f, 0.f);
#pragma unroll
        for (int o = 4; o > 0; o >>= 1) {
            v.x += __shfl_down_sync(0xffffffffu, v.x, o);
            v.y += __shfl_down_sync(0xffffffffu, v.y, o);
        }
        if (lane == 0) sh[0] = v;
    }
    __syncthreads();
    return sh[0];
}

// ---------------------------------------------------------------------------
// Embedding + LayerNorm: fp32 out + tf32-rounded copy (GEMM A operand)
// ---------------------------------------------------------------------------
__global__ void embed_ln_kernel(const int* __restrict__ ids,
                                const float* __restrict__ wemb,
                                const float* __restrict__ pemb,
                                const float* __restrict__ semb,
                                const float* __restrict__ g,
                                const float* __restrict__ bta,
                                float* __restrict__ x,
                                float* __restrict__ xT) {
    int t = blockIdx.x;
    int s = t & (Sq - 1);
    int id = ids[t];
    float v[3];
    float sum = 0.f, sq = 0.f;
#pragma unroll
    for (int i = 0; i < 3; i++) {
        int d = threadIdx.x + i * 256;
        float val = wemb[(size_t)id * Dq + d] + pemb[(size_t)s * Dq + d] + semb[d];
        v[i] = val;
        sum += val;
        sq += val * val;
    }
    float2 r = blockReduce2(sum, sq);
    float mu = r.x * (1.0f / Dq);
    float var = r.y * (1.0f / Dq) - mu * mu;
    float rstd = rsqrtf(var + 1e-5f);
#pragma unroll
    for (int i = 0; i < 3; i++) {
        int d = threadIdx.x + i * 256;
        float o = (v[i] - mu) * rstd * g[d] + bta[d];
        x[(size_t)t * Dq + d] = o;
        xT[(size_t)t * Dq + d] = T32(o);
    }
}

// ---------------------------------------------------------------------------
// out = LayerNorm(a + bvec): fp32 out + tf32-rounded copy
// ---------------------------------------------------------------------------
__global__ void add_ln_kernel(const float* __restrict__ a,
                              const float* __restrict__ bvec,
                              const float* __restrict__ g,
                              const float* __restrict__ bta,
                              float* __restrict__ out,
                              float* __restrict__ outT) {
    int t = blockIdx.x;
    float v[3];
    float sum = 0.f, sq = 0.f;
#pragma unroll
    for (int i = 0; i < 3; i++) {
        int d = threadIdx.x + i * 256;
        float val = a[(size_t)t * Dq + d] + bvec[(size_t)t * Dq + d];
        v[i] = val;
        sum += val;
        sq += val * val;
    }
    float2 r = blockReduce2(sum, sq);
    float mu = r.x * (1.0f / Dq);
    float var = r.y * (1.0f / Dq) - mu * mu;
    float rstd = rsqrtf(var + 1e-5f);
#pragma unroll
    for (int i = 0; i < 3; i++) {
        int d = threadIdx.x + i * 256;
        float o = (v[i] - mu) * rstd * g[d] + bta[d];
        out[(size_t)t * Dq + d] = o;
        outT[(size_t)t * Dq + d] = T32(o);
    }
}

// ---------------------------------------------------------------------------
// Elementwise RNE TF32 conversion (n multiple of 4)
// ---------------------------------------------------------------------------
__global__ void cvt_tf32_kernel(const float* __restrict__ in,
                                float* __restrict__ out, size_t n4) {
    size_t i = (size_t)blockIdx.x * 256 + threadIdx.x;
    if (i >= n4) return;
    float4 v = ((const float4*)in)[i];
    v.x = T32(v.x); v.y = T32(v.y); v.z = T32(v.z); v.w = T32(v.w);
    ((float4*)out)[i] = v;
}

__global__ void pad_vocab_kernel(const float* __restrict__ w,
                                 float* __restrict__ wp) {
    size_t gid = (size_t)blockIdx.x * 256 + threadIdx.x;
    size_t i4 = gid * 4;
    if (i4 >= (size_t)Dq * Npad) return;
    int k = (int)(i4 / Npad);
    int c = (int)(i4 % Npad);
    float4 v;
    v.x = (c + 0 < Vq) ? T32(w[(size_t)k * Vq + c + 0]) : 0.f;
    v.y = (c + 1 < Vq) ? T32(w[(size_t)k * Vq + c + 1]) : 0.f;
    v.z = (c + 2 < Vq) ? T32(w[(size_t)k * Vq + c + 2]) : 0.f;
    v.w = (c + 3 < Vq) ? T32(w[(size_t)k * Vq + c + 3]) : 0.f;
    *(float4*)(wp + i4) = v;
}

__global__ void pad_bias_kernel(const float* __restrict__ b,
                                float* __restrict__ bp) {
    int c = blockIdx.x * 256 + threadIdx.x;
    if (c < Npad) bp[c] = (c < Vq) ? b[c] : 0.f;
}

// ---------------------------------------------------------------------------
// TF32 WMMA GEMM, cp.async 3-stage: C[M,N] = A[M,K] @ B[K,N].
// A and B both pre-rounded tf32 (no in-loop conversion).
// 128x128 tile, BK=32, 8 warps (4 M x 2 N), warp tile 32x64.
// EPI: 0=plain direct store, 3=plain + T32 round (direct),
//      1=+bias (smem-staged), 2=+bias + exact GELU + T32 round (staged).
// ---------------------------------------------------------------------------
#define AS_LD 36
#define BS_LD 132
#define STAGE_FLOATS (128 * AS_LD + 32 * BS_LD)   // 8832
#define GEMM_SMEM_BYTES (3 * STAGE_FLOATS * 4)    // 105984

template <int EPI>
__device__ __forceinline__ void gemm_body(const float* __restrict__ A,
                                          const float* __restrict__ Bt,
                                          const float* __restrict__ bias,
                                          float* __restrict__ C,
                                          int N, int K, int ldB) {
    extern __shared__ float sm[];
    uint32_t smb = smem_u32(sm);

    int tid = threadIdx.x;
    int row0 = blockIdx.y * 128, col0 = blockIdx.x * 128;
    int warp = tid >> 5, lane = tid & 31;
    int wm = warp & 3, wn = warp >> 2;

    wmma::fragment<wmma::accumulator, 16, 16, 8, float> acc[2][4];
#pragma unroll
    for (int i = 0; i < 2; i++)
#pragma unroll
        for (int j = 0; j < 4; j++)
            wmma::fill_fragment(acc[i][j], 0.0f);

    auto issue = [&](int i) {
        int s3 = i % 3;
        uint32_t ab = smb + (uint32_t)(s3 * STAGE_FLOATS) * 4;
        uint32_t bb = ab + 128 * AS_LD * 4;
        int k0 = i << 5;
#pragma unroll
        for (int it = 0; it < 4; it++) {
            int idx = tid + it * 256;
            int r = idx >> 3, c = idx & 7;
            cp16(ab + (uint32_t)((r * AS_LD + c * 4) * 4),
                 A + (size_t)(row0 + r) * K + k0 + c * 4);
        }
#pragma unroll
        for (int it = 0; it < 4; it++) {
            int idx = tid + it * 256;
            int r = idx >> 5, c = idx & 31;
            cp16(bb + (uint32_t)((r * BS_LD + c * 4) * 4),
                 Bt + (size_t)(k0 + r) * ldB + col0 + c * 4);
        }
        cp_commit();
    };

    int niter = K >> 5;
    issue(0);
    if (niter > 1) issue(1);

    for (int i = 0; i < niter; i++) {
        if (i + 2 < niter) {
            issue(i + 2);
            cp_wait<2>();
        } else if (i + 1 < niter) {
            cp_wait<1>();
        } else {
            cp_wait<0>();
        }
        __syncthreads();

        const float* as = sm + (i % 3) * STAGE_FLOATS;
        const float* bs = as + 128 * AS_LD;
#pragma unroll
        for (int kk = 0; kk < 4; kk++) {
            wmma::fragment<wmma::matrix_a, 16, 16, 8, wmma::precision::tf32, wmma::row_major> af[2];
            wmma::fragment<wmma::matrix_b, 16, 16, 8, wmma::precision::tf32, wmma::row_major> bf[4];
#pragma unroll
            for (int ii = 0; ii < 2; ii++)
                wmma::load_matrix_sync(af[ii], as + (wm * 32 + ii * 16) * AS_LD + kk * 8, AS_LD);
#pragma unroll
            for (int j = 0; j < 4; j++)
                wmma::load_matrix_sync(bf[j], bs + (kk * 8) * BS_LD + wn * 64 + j * 16, BS_LD);
#pragma unroll
            for (int ii = 0; ii < 2; ii++)
#pragma unroll
                for (int j = 0; j < 4; j++)
                    wmma::mma_sync(acc[ii][j], af[ii], bf[j], acc[ii][j]);
        }
        __syncthreads();
    }

    if (EPI == 0 || EPI == 3) {
#pragma unroll
        for (int i = 0; i < 2; i++)
#pragma unroll
            for (int j = 0; j < 4; j++) {
                if (EPI == 3) {
#pragma unroll
                    for (int e = 0; e < acc[i][j].num_elements; e++)
                        acc[i][j].x[e] = T32(acc[i][j].x[e]);
                }
                float* dst = C + (size_t)(row0 + wm * 32 + i * 16) * N
                               + col0 + wn * 64 + j * 16;
                wmma::store_matrix_sync(dst, acc[i][j], N, wmma::mem_row_major);
            }
    } else {
        float* Cs = sm + warp * 320;  // [16][20] per warp (mainloop done)
        int rr = lane >> 1, cc = (lane & 1) * 8;
#pragma unroll
        for (int i = 0; i < 2; i++) {
#pragma unroll
            for (int j = 0; j < 4; j++) {
                wmma::store_matrix_sync(Cs, acc[i][j], 20, wmma::mem_row_major);
                __syncwarp();
                int r = row0 + wm * 32 + i * 16 + rr;
                int c0l = col0 + wn * 64 + j * 16 + cc;
                float* dst = C + (size_t)r * N + c0l;
#pragma unroll
                for (int e = 0; e < 8; e++) {
                    int c = c0l + e;
                    if (c < N) {
                        float vv = Cs[rr * 20 + cc + e];
                        vv += bias[c];
                        if (EPI == 2) {
                            vv = 0.5f * vv * (1.0f + erff(vv * 0.70710678118654752f));
                            vv = T32(vv);
                        }
                        dst[e] = vv;
                    }
                }
                __syncwarp();
            }
        }
    }
}

template <int EPI>
__global__ void __launch_bounds__(256, 2)
gemm_tf32_kernel(const float* __restrict__ A, const float* __restrict__ Bt,
                 const float* __restrict__ bias, float* __restrict__ C,
                 int N, int K, int ldB) {
    gemm_body<EPI>(A, Bt, bias, C, N, K, ldB);
}

// Batched QKV: blockIdx.z selects weight + output slab; outputs tf32-rounded
__global__ void __launch_bounds__(256, 2)
gemm_qkv_kernel(const float* __restrict__ A, const float* __restrict__ w0,
                const float* __restrict__ w1, const float* __restrict__ w2,
                float* __restrict__ c0) {
    const float* Bm = (blockIdx.z == 0) ? w0 : (blockIdx.z == 1) ? w1 : w2;
    float* C = c0 + (size_t)blockIdx.z * Tq * Dq;
    gemm_body<3>(A, Bm, nullptr, C, Dq, Dq, Dq);
}

// ---------------------------------------------------------------------------
// Fused attention scores + softmax: P[bh,q0+r,:] = softmax(scale*Q·K^T, mask)
// grid (S/32, B*H), 256 threads. Q tile 32x64; 8 key-tiles of 64; scores in
// smem [32][520]; block row softmax; single global write. q,k pre-rounded.
// ---------------------------------------------------------------------------
#define ATT_Q_FLOATS (32 * 68)
#define ATT_K_FLOATS (64 * 68)
#define ATT_SC_LD 520
#define ATT_SMEM_BYTES ((ATT_Q_FLOATS + ATT_K_FLOATS + 32 * ATT_SC_LD) * 4)

__global__ void __launch_bounds__(256)
attn_scores_softmax(const float* __restrict__ q, const float* __restrict__ k,
                    const int* __restrict__ mask, float* __restrict__ out) {
    extern __shared__ float fsm[];
    float* Qs = fsm;                       // [32][68]
    float* Ks = Qs + ATT_Q_FLOATS;         // [64][68]
    float* Sc = Ks + ATT_K_FLOATS;         // [32][520]

    int bh = blockIdx.y;
    int b = bh / Hq, h = bh % Hq;
    int q0 = blockIdx.x * 32;
    int tid = threadIdx.x;
    int warp = tid >> 5, lane = tid & 31;
    int wm = warp & 1, wn = warp >> 1;     // 2 m-warps x 4 n-warps

#pragma unroll
    for (int i = 0; i < 2; i++) {
        int idx = tid + i * 256;
        int r = idx >> 4, c4 = (idx & 15) * 4;
        float4 v = *(const float4*)(q + (size_t)(b * Sq + q0 + r) * Dq + h * HDq + c4);
        Qs[r * 68 + c4 + 0] = v.x; Qs[r * 68 + c4 + 1] = v.y;
        Qs[r * 68 + c4 + 2] = v.z; Qs[r * 68 + c4 + 3] = v.w;
    }

    for (int kt = 0; kt < 8; kt++) {
        __syncthreads();
#pragma unroll
        for (int i = 0; i < 4; i++) {
            int idx = tid + i * 256;
            int r = idx >> 4, c4 = (idx & 15) * 4;
            float4 v = *(const float4*)(k + (size_t)(b * Sq + kt * 64 + r) * Dq + h * HDq + c4);
            Ks[r * 68 + c4 + 0] = v.x; Ks[r * 68 + c4 + 1] = v.y;
            Ks[r * 68 + c4 + 2] = v.z; Ks[r * 68 + c4 + 3] = v.w;
        }
        __syncthreads();

        wmma::fragment<wmma::accumulator, 16, 16, 8, float> acc;
        wmma::fill_fragment(acc, 0.0f);
#pragma unroll
        for (int kk = 0; kk < 8; kk++) {
            wmma::fragment<wmma::matrix_a, 16, 16, 8, wmma::precision::tf32, wmma::row_major> af;
            wmma::fragment<wmma::matrix_b, 16, 16, 8, wmma::precision::tf32, wmma::col_major> bf;
            wmma::load_matrix_sync(af, Qs + (wm * 16) * 68 + kk * 8, 68);
            wmma::load_matrix_sync(bf, Ks + (wn * 16) * 68 + kk * 8, 68);
            wmma::mma_sync(acc, af, bf, acc);
        }
        wmma::store_matrix_sync(Sc + (wm * 16) * ATT_SC_LD + kt * 64 + wn * 16,
                                acc, ATT_SC_LD, wmma::mem_row_major);
    }
    __syncthreads();

    const float scale = 0.03608439182435161f;  // 1/sqrt(D=768)
#pragma unroll
    for (int i = 0; i < 4; i++) {
        int r = warp * 4 + i;
        float v[16];
        float m = -INFINITY;
#pragma unroll
        for (int j = 0; j < 16; j++) {
            int col = lane + j * 32;
            float f = Sc[r * ATT_SC_LD + col] * scale;
            if (mask[b * Sq + col] == 0) f = -INFINITY;
            v[j] = f;
            m = fmaxf(m, f);
        }
#pragma unroll
        for (int o = 16; o > 0; o >>= 1) m = fmaxf(m, __shfl_xor_sync(0xffffffffu, m, o));
        float s = 0.f;
#pragma unroll
        for (int j = 0; j < 16; j++) {
            v[j] = __expf(v[j] - m);
            s += v[j];
        }
#pragma unroll
        for (int o = 16; o > 0; o >>= 1) s += __shfl_xor_sync(0xffffffffu, s, o);
        float inv = 1.0f / s;
        float* dst = out + ((size_t)bh * Sq + q0 + r) * Sq;
#pragma unroll
        for (int j = 0; j < 16; j++) dst[lane + j * 32] = v[j] * inv;
    }
}

// ---------------------------------------------------------------------------
// o[b,q,h*64+d] = sum_k P[bh,q,k] * V[b,k,h*64+d]   (TF32 wmma)
// P converted at load; V pre-rounded; output tf32-rounded (feeds O-proj A).
// ---------------------------------------------------------------------------
__global__ void __launch_bounds__(256)
attn_av_tf32(const float* __restrict__ p, const float* __restrict__ v,
             float* __restrict__ o) {
    __shared__ float Ps[64][36];
    __shared__ float Vs[32][68];
    __shared__ float Cs[8][16][20];
    int bh = blockIdx.z;
    int b = bh / Hq, h = bh % Hq;
    int q0 = blockIdx.y * 64;
    int tid = threadIdx.x;
    int warp = tid >> 5, lane = tid & 31;
    int wm = warp & 3, wn = warp >> 2;

    wmma::fragment<wmma::accumulator, 16, 16, 8, float> acc[2];
    wmma::fill_fragment(acc[0], 0.0f);
    wmma::fill_fragment(acc[1], 0.0f);

    for (int k0 = 0; k0 < Sq; k0 += 32) {
#pragma unroll
        for (int i = 0; i < 2; i++) {
            int idx = tid + i * 256;
            int pr = idx >> 3, pc4 = (idx & 7) * 4;
            float4 pv = *(const float4*)(p + ((size_t)bh * Sq + q0 + pr) * Sq + k0 + pc4);
            Ps[pr][pc4 + 0] = T32(pv.x); Ps[pr][pc4 + 1] = T32(pv.y);
            Ps[pr][pc4 + 2] = T32(pv.z); Ps[pr][pc4 + 3] = T32(pv.w);
            int vr = idx >> 4, vc4 = (idx & 15) * 4;
            float4 vv = *(const float4*)(v + (size_t)(b * Sq + k0 + vr) * Dq + h * HDq + vc4);
            Vs[vr][vc4 + 0] = vv.x; Vs[vr][vc4 + 1] = vv.y;
            Vs[vr][vc4 + 2] = vv.z; Vs[vr][vc4 + 3] = vv.w;
        }
        __syncthreads();
#pragma unroll
        for (int kk = 0; kk < 4; kk++) {
            wmma::fragment<wmma::matrix_a, 16, 16, 8, wmma::precision::tf32, wmma::row_major> af;
            wmma::load_matrix_sync(af, &Ps[wm * 16][kk * 8], 36);
#pragma unroll
            for (int j = 0; j < 2; j++) {
                wmma::fragment<wmma::matrix_b, 16, 16, 8, wmma::precision::tf32, wmma::row_major> bf;
                wmma::load_matrix_sync(bf, &Vs[kk * 8][wn * 32 + j * 16], 68);
                wmma::mma_sync(acc[j], af, bf, acc[j]);
            }
        }
        __syncthreads();
    }

    int rr = lane >> 1, cc = (lane & 1) * 8;
#pragma unroll
    for (int j = 0; j < 2; j++) {
        wmma::store_matrix_sync(&Cs[warp][0][0], acc[j], 20, wmma::mem_row_major);
        __syncwarp();
        int qr = q0 + wm * 16 + rr;
        int dc = h * HDq + wn * 32 + j * 16 + cc;
        float* dst = o + (size_t)(b * Sq + qr) * Dq + dc;
#pragma unroll
        for (int e = 0; e < 8; e++) dst[e] = T32(Cs[warp][rr][cc + e]);
        __syncwarp();
    }
}

// ---------------------------------------------------------------------------
// Host orchestration (graph-capturable: kernel launches only)
// ---------------------------------------------------------------------------
extern "C" void kernel_launch(void* const* d_in, const int* in_sizes, int n_in,
                              void* d_out, int out_size) {
    const int*   ids  = (const int*)d_in[0];
    const int*   mask = (const int*)d_in[1];
    const float* wemb = (const float*)d_in[2];
    const float* pemb = (const float*)d_in[3];
    const float* semb = (const float*)d_in[4];
    const float* elng = (const float*)d_in[5];
    const float* elnb = (const float*)d_in[6];
    const float* Wq   = (const float*)d_in[7];
    const float* Wk   = (const float*)d_in[8];
    const float* Wv   = (const float*)d_in[9];
    const float* Wo   = (const float*)d_in[10];
    const float* f1w  = (const float*)d_in[11];
    const float* f1b  = (const float*)d_in[12];
    const float* f2w  = (const float*)d_in[13];
    const float* f2b  = (const float*)d_in[14];
    const float* l1g  = (const float*)d_in[15];
    const float* l1b  = (const float*)d_in[16];
    const float* l2g  = (const float*)d_in[17];
    const float* l2b  = (const float*)d_in[18];
    const float* outw = (const float*)d_in[19];
    const float* outb = (const float*)d_in[20];

    static bool attr_done = false;
    if (!attr_done) {
        cudaFuncSetAttribute(gemm_tf32_kernel<0>, cudaFuncAttributeMaxDynamicSharedMemorySize, GEMM_SMEM_BYTES);
        cudaFuncSetAttribute(gemm_tf32_kernel<1>, cudaFuncAttributeMaxDynamicSharedMemorySize, GEMM_SMEM_BYTES);
        cudaFuncSetAttribute(gemm_tf32_kernel<2>, cudaFuncAttributeMaxDynamicSharedMemorySize, GEMM_SMEM_BYTES);
        cudaFuncSetAttribute(gemm_tf32_kernel<3>, cudaFuncAttributeMaxDynamicSharedMemorySize, GEMM_SMEM_BYTES);
        cudaFuncSetAttribute(gemm_qkv_kernel,     cudaFuncAttributeMaxDynamicSharedMemorySize, GEMM_SMEM_BYTES);
        cudaFuncSetAttribute(attn_scores_softmax, cudaFuncAttributeMaxDynamicSharedMemorySize, ATT_SMEM_BYTES);
        attr_done = true;
    }

    float* ws = nullptr;
    cudaGetSymbolAddress((void**)&ws, g_ws);
    float* x    = ws;
    float* xT   = x   + (size_t)Tq * Dq;
    float* x1   = xT  + (size_t)Tq * Dq;
    float* x1T  = x1  + (size_t)Tq * Dq;
    float* q    = x1T + (size_t)Tq * Dq;
    float* kb   = q   + (size_t)Tq * Dq;
    float* vb   = kb  + (size_t)Tq * Dq;
    float* tb   = vb  + (size_t)Tq * Dq;
    float* hb   = tb  + (size_t)Tq * Dq;
    float* wpad = hb  + (size_t)Tq * Fq;
    float* bpad = wpad + (size_t)Dq * Npad;
    float* cWq  = bpad + Npad;
    float* cWk  = cWq + LDD;
    float* cWv  = cWk + LDD;
    float* cWo  = cWv + LDD;
    float* cF1  = cWo + LDD;
    float* cF2  = cF1 + LDF;

    float* logits = (float*)d_out;                       // [B*S, V]
    float* attn   = logits + (size_t)Tq * Vq;            // [L, B*H, S, S]

    // ---- pre-round weights to TF32 + pad vocab ----
    {
        size_t n4dd = LDD / 4;
        unsigned gdd = (unsigned)((n4dd + 255) / 256);
        cvt_tf32_kernel<<<gdd, 256>>>(Wq, cWq, n4dd);
        cvt_tf32_kernel<<<gdd, 256>>>(Wk, cWk, n4dd);
        cvt_tf32_kernel<<<gdd, 256>>>(Wv, cWv, n4dd);
        cvt_tf32_kernel<<<gdd, 256>>>(Wo, cWo, n4dd);
        size_t n4df = LDF / 4;
        unsigned gdf = (unsigned)((n4df + 255) / 256);
        cvt_tf32_kernel<<<gdf, 256>>>(f1w, cF1, n4df);
        cvt_tf32_kernel<<<gdf, 256>>>(f2w, cF2, n4df);
        size_t n4v = ((size_t)Dq * Npad) / 4;
        pad_vocab_kernel<<<(unsigned)((n4v + 255) / 256), 256>>>(outw, wpad);
        pad_bias_kernel<<<(Npad + 255) / 256, 256>>>(outb, bpad);
    }

    embed_ln_kernel<<<Tq, 256>>>(ids, wemb, pemb, semb, elng, elnb, x, xT);

    for (int l = 0; l < Lq; l++) {
        float* slab = attn + (size_t)l * Bq * Hq * Sq * Sq;
        dim3 gDD(Dq / 128, Tq / 128);  // (6,16)

        gemm_qkv_kernel<<<dim3(Dq / 128, Tq / 128, 3), 256, GEMM_SMEM_BYTES>>>(
            xT, cWq + (size_t)l * Dq * Dq, cWk + (size_t)l * Dq * Dq,
            cWv + (size_t)l * Dq * Dq, q);

        attn_scores_softmax<<<dim3(Sq / 32, Bq * Hq), 256, ATT_SMEM_BYTES>>>(
            q, kb, mask, slab);
        attn_av_tf32<<<dim3(1, Sq / 64, Bq * Hq), 256>>>(slab, vb, tb);

        gemm_tf32_kernel<0><<<gDD, 256, GEMM_SMEM_BYTES>>>(
            tb, cWo + (size_t)l * Dq * Dq, nullptr, q, Dq, Dq, Dq);
        add_ln_kernel<<<Tq, 256>>>(x, q, l1g + (size_t)l * Dq, l1b + (size_t)l * Dq, x1, x1T);

        gemm_tf32_kernel<2><<<dim3(Fq / 128, Tq / 128), 256, GEMM_SMEM_BYTES>>>(
            x1T, cF1 + (size_t)l * Dq * Fq, f1b + (size_t)l * Fq, hb, Fq, Dq, Fq);
        gemm_tf32_kernel<1><<<dim3(Dq / 128, Tq / 128), 256, GEMM_SMEM_BYTES>>>(
            hb, cF2 + (size_t)l * Fq * Dq, f2b + (size_t)l * Dq, tb, Dq, Fq, Dq);
        add_ln_kernel<<<Tq, 256>>>(x1, tb, l2g + (size_t)l * Dq, l2b + (size_t)l * Dq, x, xT);
    }

    gemm_tf32_kernel<1><<<dim3(Npad / 128, Tq / 128), 256, GEMM_SMEM_BYTES>>>(
        xT, wpad, bpad, logits, Vq, Dq, Npad);
}

// round 13
// speedup vs baseline: 3.0217x; 2.4301x over previous
#include <cuda_runtime.h>
#include <mma.h>
#include <math.h>
#include <cstdint>
#include <cuda_fp16.h>

using namespace nvcuda;

// BERT-base forward: B=4, S=512, L=12, D=768, H=12, F=3072, V=30522
#define Bq 4
#define Sq 512
#define Lq 12
#define Dq 768
#define Hq 12
#define Fq 3072
#define Vq 30522
#define HDq 64
#define Tq 2048    // B*S tokens
#define Npad 30592 // 239*128, padded vocab width

#define LDD ((size_t)Lq * Dq * Dq)
#define LDF ((size_t)Lq * Dq * Fq)

// fp32 workspace: x, x1, tmp32 [T,D]; bpad [Npad]
__device__ float g_ws[3 * (size_t)Tq * Dq + Npad];
// fp16 workspace: xH,x1H,qH,kH,vH,tbH [T,D]; hbH [T,F]; wpadH [D,Npad];
// hWq,hWk,hWv,hWo [L,D,D]; hF1 [L,D,F]; hF2 [L,F,D]
__device__ __half g_hws[6 * (size_t)Tq * Dq + (size_t)Tq * Fq
                        + (size_t)Dq * Npad + 4 * LDD + 2 * LDF];

__device__ __forceinline__ __half H16(float x) { return __float2half_rn(x); }

__device__ __forceinline__ void cp16(uint32_t dst, const void* src) {
    asm volatile("cp.async.cg.shared.global [%0], [%1], 16;" :: "r"(dst), "l"(src));
}
__device__ __forceinline__ void cp_commit() {
    asm volatile("cp.async.commit_group;");
}
template <int N>
__device__ __forceinline__ void cp_wait() {
    asm volatile("cp.async.wait_group %0;" :: "n"(N));
}
__device__ __forceinline__ uint32_t smem_u32(const void* p) {
    return (uint32_t)__cvta_generic_to_shared(p);
}

// ---------------------------------------------------------------------------
// Block-wide sum of (a,b) pairs, 256 threads
// ---------------------------------------------------------------------------
__device__ __forceinline__ float2 blockReduce2(float a, float b) {
#pragma unroll
    for (int o = 16; o > 0; o >>= 1) {
        a += __shfl_down_sync(0xffffffffu, a, o);
        b += __shfl_down_sync(0xffffffffu, b, o);
    }
    __shared__ float2 sh[8];
    int lane = threadIdx.x & 31, wid = threadIdx.x >> 5;
    if (lane == 0) sh[wid] = make_float2(a, b);
    __syncthreads();
    if (wid == 0) {
        float2 v = (lane < 8) ? sh[lane] : make_float2(0.f, 0.f);
#pragma unroll
        for (int o = 4; o > 0; o >>= 1) {
            v.x += __shfl_down_sync(0xffffffffu, v.x, o);
            v.y += __shfl_down_sync(0xffffffffu, v.y, o);
        }
        if (lane == 0) sh[0] = v;
    }
    __syncthreads();
    return sh[0];
}

// ---------------------------------------------------------------------------
// Embedding + LayerNorm: fp32 out + fp16-rounded copy (GEMM A operand)
// ---------------------------------------------------------------------------
__global__ void embed_ln_kernel(const int* __restrict__ ids,
                                const float* __restrict__ wemb,
                                const float* __restrict__ pemb,
                                const float* __restrict__ semb,
                                const float* __restrict__ g,
                                const float* __restrict__ bta,
                                float* __restrict__ x,
                                __half* __restrict__ xH) {
    int t = blockIdx.x;
    int s = t & (Sq - 1);
    int id = ids[t];
    float v[3];
    float sum = 0.f, sq = 0.f;
#pragma unroll
    for (int i = 0; i < 3; i++) {
        int d = threadIdx.x + i * 256;
        float val = wemb[(size_t)id * Dq + d] + pemb[(size_t)s * Dq + d] + semb[d];
        v[i] = val;
        sum += val;
        sq += val * val;
    }
    float2 r = blockReduce2(sum, sq);
    float mu = r.x * (1.0f / Dq);
    float var = r.y * (1.0f / Dq) - mu * mu;
    float rstd = rsqrtf(var + 1e-5f);
#pragma unroll
    for (int i = 0; i < 3; i++) {
        int d = threadIdx.x + i * 256;
        float o = (v[i] - mu) * rstd * g[d] + bta[d];
        x[(size_t)t * Dq + d] = o;
        xH[(size_t)t * Dq + d] = H16(o);
    }
}

// ---------------------------------------------------------------------------
// out = LayerNorm(a + bvec): fp32 out + fp16-rounded copy
// ---------------------------------------------------------------------------
__global__ void add_ln_kernel(const float* __restrict__ a,
                              const float* __restrict__ bvec,
                              const float* __restrict__ g,
                              const float* __restrict__ bta,
                              float* __restrict__ out,
                              __half* __restrict__ outH) {
    int t = blockIdx.x;
    float v[3];
    float sum = 0.f, sq = 0.f;
#pragma unroll
    for (int i = 0; i < 3; i++) {
        int d = threadIdx.x + i * 256;
        float val = a[(size_t)t * Dq + d] + bvec[(size_t)t * Dq + d];
        v[i] = val;
        sum += val;
        sq += val * val;
    }
    float2 r = blockReduce2(sum, sq);
    float mu = r.x * (1.0f / Dq);
    float var = r.y * (1.0f / Dq) - mu * mu;
    float rstd = rsqrtf(var + 1e-5f);
#pragma unroll
    for (int i = 0; i < 3; i++) {
        int d = threadIdx.x + i * 256;
        float o = (v[i] - mu) * rstd * g[d] + bta[d];
        out[(size_t)t * Dq + d] = o;
        outH[(size_t)t * Dq + d] = H16(o);
    }
}

// ---------------------------------------------------------------------------
// Elementwise fp32 -> fp16 (RNE), n multiple of 4
// ---------------------------------------------------------------------------
__global__ void cvt_half_kernel(const float* __restrict__ in,
                                __half* __restrict__ out, size_t n4) {
    size_t i = (size_t)blockIdx.x * 256 + threadIdx.x;
    if (i >= n4) return;
    float4 v = ((const float4*)in)[i];
    __half2 h0 = __floats2half2_rn(v.x, v.y);
    __half2 h1 = __floats2half2_rn(v.z, v.w);
    ((__half2*)out)[i * 2 + 0] = h0;
    ((__half2*)out)[i * 2 + 1] = h1;
}

__global__ void pad_vocab_kernel(const float* __restrict__ w,
                                 __half* __restrict__ wp) {
    size_t gid = (size_t)blockIdx.x * 256 + threadIdx.x;
    size_t i4 = gid * 4;
    if (i4 >= (size_t)Dq * Npad) return;
    int k = (int)(i4 / Npad);
    int c = (int)(i4 % Npad);
    float a = (c + 0 < Vq) ? w[(size_t)k * Vq + c + 0] : 0.f;
    float b = (c + 1 < Vq) ? w[(size_t)k * Vq + c + 1] : 0.f;
    float d = (c + 2 < Vq) ? w[(size_t)k * Vq + c + 2] : 0.f;
    float e = (c + 3 < Vq) ? w[(size_t)k * Vq + c + 3] : 0.f;
    ((__half2*)wp)[gid * 2 + 0] = __floats2half2_rn(a, b);
    ((__half2*)wp)[gid * 2 + 1] = __floats2half2_rn(d, e);
}

__global__ void pad_bias_kernel(const float* __restrict__ b,
                                float* __restrict__ bp) {
    int c = blockIdx.x * 256 + threadIdx.x;
    if (c < Npad) bp[c] = (c < Vq) ? b[c] : 0.f;
}

// ---------------------------------------------------------------------------
// FP16 WMMA GEMM, cp.async 4-stage: C[M,N] = A[M,K] @ B[K,N], fp32 accum.
// 128x128 tile, BK=32, 8 warps (4 M x 2 N), warp tile 32x64, m16n16k16.
// MODE: 0 = float out, plain (direct frag store)
//       1 = float out, +bias (staged)
//       2 = half out, +bias + exact GELU (staged)
//       3 = half out, plain (staged)
// ---------------------------------------------------------------------------
#define AS_LD 40
#define BS_LD 136
#define STAGE_HALFS (128 * AS_LD + 32 * BS_LD)        // 9472
#define GEMM_SMEM_BYTES (4 * STAGE_HALFS * 2)         // 75776

template <int MODE>
__device__ __forceinline__ void gemm_body(const __half* __restrict__ A,
                                          const __half* __restrict__ Bt,
                                          const float* __restrict__ bias,
                                          void* __restrict__ Cv,
                                          int N, int K, int ldB) {
    extern __shared__ char smraw[];
    __half* smh = (__half*)smraw;
    float* smf = (float*)smraw;
    uint32_t smb = smem_u32(smraw);

    int tid = threadIdx.x;
    int row0 = blockIdx.y * 128, col0 = blockIdx.x * 128;
    int warp = tid >> 5, lane = tid & 31;
    int wm = warp & 3, wn = warp >> 2;

    wmma::fragment<wmma::accumulator, 16, 16, 16, float> acc[2][4];
#pragma unroll
    for (int i = 0; i < 2; i++)
#pragma unroll
        for (int j = 0; j < 4; j++)
            wmma::fill_fragment(acc[i][j], 0.0f);

    auto issue = [&](int i) {
        uint32_t sb = smb + (uint32_t)((i & 3) * STAGE_HALFS) * 2;
        uint32_t bb = sb + 128 * AS_LD * 2;
        int k0 = i << 5;
        // A: 128 rows x 4 groups of 8 halves = 512 tasks, 2/thread
#pragma unroll
        for (int it = 0; it < 2; it++) {
            int idx = tid + it * 256;
            int r = idx >> 2, c = idx & 3;
            cp16(sb + (uint32_t)((r * AS_LD + c * 8) * 2),
                 A + (size_t)(row0 + r) * K + k0 + c * 8);
        }
        // B: 32 rows x 16 groups of 8 halves = 512 tasks, 2/thread
#pragma unroll
        for (int it = 0; it < 2; it++) {
            int idx = tid + it * 256;
            int r = idx >> 4, c = idx & 15;
            cp16(bb + (uint32_t)((r * BS_LD + c * 8) * 2),
                 Bt + (size_t)(k0 + r) * ldB + col0 + c * 8);
        }
        cp_commit();
    };

    int niter = K >> 5;
    issue(0);
    if (niter > 1) issue(1);
    if (niter > 2) issue(2);

    for (int i = 0; i < niter; i++) {
        if (i + 3 < niter) {
            issue(i + 3);
            cp_wait<3>();
        } else if (i + 2 < niter) {
            cp_wait<2>();
        } else if (i + 1 < niter) {
            cp_wait<1>();
        } else {
            cp_wait<0>();
        }
        __syncthreads();

        const __half* as = smh + (i & 3) * STAGE_HALFS;
        const __half* bs = as + 128 * AS_LD;
#pragma unroll
        for (int kk = 0; kk < 2; kk++) {
            wmma::fragment<wmma::matrix_a, 16, 16, 16, __half, wmma::row_major> af[2];
            wmma::fragment<wmma::matrix_b, 16, 16, 16, __half, wmma::row_major> bf[4];
#pragma unroll
            for (int ii = 0; ii < 2; ii++)
                wmma::load_matrix_sync(af[ii], as + (wm * 32 + ii * 16) * AS_LD + kk * 16, AS_LD);
#pragma unroll
            for (int j = 0; j < 4; j++)
                wmma::load_matrix_sync(bf[j], bs + (kk * 16) * BS_LD + wn * 64 + j * 16, BS_LD);
#pragma unroll
            for (int ii = 0; ii < 2; ii++)
#pragma unroll
                for (int j = 0; j < 4; j++)
                    wmma::mma_sync(acc[ii][j], af[ii], bf[j], acc[ii][j]);
        }
        __syncthreads();
    }

    if (MODE == 0) {
        float* C = (float*)Cv;
#pragma unroll
        for (int i = 0; i < 2; i++)
#pragma unroll
            for (int j = 0; j < 4; j++) {
                float* dst = C + (size_t)(row0 + wm * 32 + i * 16) * N
                               + col0 + wn * 64 + j * 16;
                wmma::store_matrix_sync(dst, acc[i][j], N, wmma::mem_row_major);
            }
    } else {
        float* Cs = smf + warp * 320;  // [16][20] per warp (mainloop done)
        int rr = lane >> 1, cc = (lane & 1) * 8;
#pragma unroll
        for (int i = 0; i < 2; i++) {
#pragma unroll
            for (int j = 0; j < 4; j++) {
                wmma::store_matrix_sync(Cs, acc[i][j], 20, wmma::mem_row_major);
                __syncwarp();
                int r = row0 + wm * 32 + i * 16 + rr;
                int c0l = col0 + wn * 64 + j * 16 + cc;
#pragma unroll
                for (int e = 0; e < 8; e++) {
                    int c = c0l + e;
                    if (c < N) {
                        float vv = Cs[rr * 20 + cc + e];
                        if (MODE == 1 || MODE == 2) vv += bias[c];
                        if (MODE == 2)
                            vv = 0.5f * vv * (1.0f + erff(vv * 0.70710678118654752f));
                        if (MODE == 1)
                            ((float*)Cv)[(size_t)r * N + c] = vv;
                        else
                            ((__half*)Cv)[(size_t)r * N + c] = H16(vv);
                    }
                }
                __syncwarp();
            }
        }
    }
}

template <int MODE>
__global__ void __launch_bounds__(256, 2)
gemm_h_kernel(const __half* __restrict__ A, const __half* __restrict__ Bt,
              const float* __restrict__ bias, void* __restrict__ Cv,
              int N, int K, int ldB) {
    gemm_body<MODE>(A, Bt, bias, Cv, N, K, ldB);
}

// Batched QKV: blockIdx.z selects weight + output slab; outputs half
__global__ void __launch_bounds__(256, 2)
gemm_qkv_kernel(const __half* __restrict__ A, const __half* __restrict__ w0,
                const __half* __restrict__ w1, const __half* __restrict__ w2,
                __half* __restrict__ c0) {
    const __half* Bm = (blockIdx.z == 0) ? w0 : (blockIdx.z == 1) ? w1 : w2;
    __half* C = c0 + (size_t)blockIdx.z * Tq * Dq;
    gemm_body<3>(A, Bm, nullptr, (void*)C, Dq, Dq, Dq);
}

// ---------------------------------------------------------------------------
// Fused attention scores + softmax (fp16 MMA, fp32 softmax):
// P[bh,q0+r,:] = softmax(scale * Q K^T, mask). grid (S/32, B*H), 256 thr.
// ---------------------------------------------------------------------------
#define ATTQ_HALFS (32 * 72)
#define ATTK_HALFS (64 * 72)
#define ATT_SC_LD 520
#define ATT_SMEM_BYTES ((ATTQ_HALFS + ATTK_HALFS) * 2 + 32 * ATT_SC_LD * 4)

__global__ void __launch_bounds__(256)
attn_scores_softmax(const __half* __restrict__ q, const __half* __restrict__ k,
                    const int* __restrict__ mask, float* __restrict__ out) {
    extern __shared__ char asmraw[];
    __half* Qs = (__half*)asmraw;                 // [32][72]
    __half* Ks = Qs + ATTQ_HALFS;                 // [64][72]
    float* Sc = (float*)(asmraw + (ATTQ_HALFS + ATTK_HALFS) * 2);  // [32][520]

    int bh = blockIdx.y;
    int b = bh / Hq, h = bh % Hq;
    int q0 = blockIdx.x * 32;
    int tid = threadIdx.x;
    int warp = tid >> 5, lane = tid & 31;
    int wm = warp & 1, wn = warp >> 1;            // 2 m-warps x 4 n-warps

    // load Q tile 32x64 halves: 256 tasks of 8 halves, 1/thread
    {
        int r = tid >> 3, c = tid & 7;
        *(uint4*)(Qs + r * 72 + c * 8) =
            *(const uint4*)(q + (size_t)(b * Sq + q0 + r) * Dq + h * HDq + c * 8);
    }

    for (int kt = 0; kt < 8; kt++) {
        __syncthreads();
#pragma unroll
        for (int i = 0; i < 2; i++) {
            int idx = tid + i * 256;
            int r = idx >> 3, c = idx & 7;
            *(uint4*)(Ks + r * 72 + c * 8) =
                *(const uint4*)(k + (size_t)(b * Sq + kt * 64 + r) * Dq + h * HDq + c * 8);
        }
        __syncthreads();

        wmma::fragment<wmma::accumulator, 16, 16, 16, float> acc;
        wmma::fill_fragment(acc, 0.0f);
#pragma unroll
        for (int kk = 0; kk < 4; kk++) {
            wmma::fragment<wmma::matrix_a, 16, 16, 16, __half, wmma::row_major> af;
            wmma::fragment<wmma::matrix_b, 16, 16, 16, __half, wmma::col_major> bf;
            wmma::load_matrix_sync(af, Qs + (wm * 16) * 72 + kk * 16, 72);
            wmma::load_matrix_sync(bf, Ks + (wn * 16) * 72 + kk * 16, 72);
            wmma::mma_sync(acc, af, bf, acc);
        }
        wmma::store_matrix_sync(Sc + (wm * 16) * ATT_SC_LD + kt * 64 + wn * 16,
                                acc, ATT_SC_LD, wmma::mem_row_major);
    }
    __syncthreads();

    const float scale = 0.03608439182435161f;  // 1/sqrt(D=768)
#pragma unroll
    for (int i = 0; i < 4; i++) {
        int r = warp * 4 + i;
        float v[16];
        float m = -INFINITY;
#pragma unroll
        for (int j = 0; j < 16; j++) {
            int col = lane + j * 32;
            float f = Sc[r * ATT_SC_LD + col] * scale;
            if (mask[b * Sq + col] == 0) f = -INFINITY;
            v[j] = f;
            m = fmaxf(m, f);
        }
#pragma unroll
        for (int o = 16; o > 0; o >>= 1) m = fmaxf(m, __shfl_xor_sync(0xffffffffu, m, o));
        float s = 0.f;
#pragma unroll
        for (int j = 0; j < 16; j++) {
            v[j] = __expf(v[j] - m);
            s += v[j];
        }
#pragma unroll
        for (int o = 16; o > 0; o >>= 1) s += __shfl_xor_sync(0xffffffffu, s, o);
        float inv = 1.0f / s;
        float* dst = out + ((size_t)bh * Sq + q0 + r) * Sq;
#pragma unroll
        for (int j = 0; j < 16; j++) dst[lane + j * 32] = v[j] * inv;
    }
}

// ---------------------------------------------------------------------------
// o[b,q,h*64+d] = sum_k P[bh,q,k] * V[b,k,h*64+d]   (fp16 MMA, fp32 accum)
// P fp32 -> half at smem store; V half; output half (feeds O-proj A).
// ---------------------------------------------------------------------------
__global__ void __launch_bounds__(256)
attn_av_h(const float* __restrict__ p, const __half* __restrict__ v,
          __half* __restrict__ o) {
    __shared__ __half Ps[64][40];
    __shared__ __half Vs[32][72];
    __shared__ float Cs[8][16][20];
    int bh = blockIdx.z;
    int b = bh / Hq, h = bh % Hq;
    int q0 = blockIdx.y * 64;
    int tid = threadIdx.x;
    int warp = tid >> 5, lane = tid & 31;
    int wm = warp & 3, wn = warp >> 2;

    wmma::fragment<wmma::accumulator, 16, 16, 16, float> acc[2];
    wmma::fill_fragment(acc[0], 0.0f);
    wmma::fill_fragment(acc[1], 0.0f);

    for (int k0 = 0; k0 < Sq; k0 += 32) {
        // P: 64 rows x 8 groups of 4 floats = 512 tasks, 2/thread
#pragma unroll
        for (int i = 0; i < 2; i++) {
            int idx = tid + i * 256;
            int pr = idx >> 3, pc = (idx & 7) * 4;
            float4 pv = *(const float4*)(p + ((size_t)bh * Sq + q0 + pr) * Sq + k0 + pc);
            Ps[pr][pc + 0] = H16(pv.x); Ps[pr][pc + 1] = H16(pv.y);
            Ps[pr][pc + 2] = H16(pv.z); Ps[pr][pc + 3] = H16(pv.w);
        }
        // V: 32 rows x 8 groups of 8 halves = 256 tasks, 1/thread
        {
            int vr = tid >> 3, vc = tid & 7;
            *(uint4*)(&Vs[vr][vc * 8]) =
                *(const uint4*)(v + (size_t)(b * Sq + k0 + vr) * Dq + h * HDq + vc * 8);
        }
        __syncthreads();
#pragma unroll
        for (int kk = 0; kk < 2; kk++) {
            wmma::fragment<wmma::matrix_a, 16, 16, 16, __half, wmma::row_major> af;
            wmma::load_matrix_sync(af, &Ps[wm * 16][kk * 16], 40);
#pragma unroll
            for (int j = 0; j < 2; j++) {
                wmma::fragment<wmma::matrix_b, 16, 16, 16, __half, wmma::row_major> bf;
                wmma::load_matrix_sync(bf, &Vs[kk * 16][wn * 32 + j * 16], 72);
                wmma::mma_sync(acc[j], af, bf, acc[j]);
            }
        }
        __syncthreads();
    }

    int rr = lane >> 1, cc = (lane & 1) * 8;
#pragma unroll
    for (int j = 0; j < 2; j++) {
        wmma::store_matrix_sync(&Cs[warp][0][0], acc[j], 20, wmma::mem_row_major);
        __syncwarp();
        int qr = q0 + wm * 16 + rr;
        int dc = h * HDq + wn * 32 + j * 16 + cc;
        __half* dst = o + (size_t)(b * Sq + qr) * Dq + dc;
#pragma unroll
        for (int e = 0; e < 8; e++) dst[e] = H16(Cs[warp][rr][cc + e]);
        __syncwarp();
    }
}

// ---------------------------------------------------------------------------
// Host orchestration (graph-capturable: kernel launches only)
// ---------------------------------------------------------------------------
extern "C" void kernel_launch(void* const* d_in, const int* in_sizes, int n_in,
                              void* d_out, int out_size) {
    const int*   ids  = (const int*)d_in[0];
    const int*   mask = (const int*)d_in[1];
    const float* wemb = (const float*)d_in[2];
    const float* pemb = (const float*)d_in[3];
    const float* semb = (const float*)d_in[4];
    const float* elng = (const float*)d_in[5];
    const float* elnb = (const float*)d_in[6];
    const float* Wq   = (const float*)d_in[7];
    const float* Wk   = (const float*)d_in[8];
    const float* Wv   = (const float*)d_in[9];
    const float* Wo   = (const float*)d_in[10];
    const float* f1w  = (const float*)d_in[11];
    const float* f1b  = (const float*)d_in[12];
    const float* f2w  = (const float*)d_in[13];
    const float* f2b  = (const float*)d_in[14];
    const float* l1g  = (const float*)d_in[15];
    const float* l1b  = (const float*)d_in[16];
    const float* l2g  = (const float*)d_in[17];
    const float* l2b  = (const float*)d_in[18];
    const float* outw = (const float*)d_in[19];
    const float* outb = (const float*)d_in[20];

    static bool attr_done = false;
    if (!attr_done) {
        cudaFuncSetAttribute(gemm_h_kernel<0>, cudaFuncAttributeMaxDynamicSharedMemorySize, GEMM_SMEM_BYTES);
        cudaFuncSetAttribute(gemm_h_kernel<1>, cudaFuncAttributeMaxDynamicSharedMemorySize, GEMM_SMEM_BYTES);
        cudaFuncSetAttribute(gemm_h_kernel<2>, cudaFuncAttributeMaxDynamicSharedMemorySize, GEMM_SMEM_BYTES);
        cudaFuncSetAttribute(gemm_h_kernel<3>, cudaFuncAttributeMaxDynamicSharedMemorySize, GEMM_SMEM_BYTES);
        cudaFuncSetAttribute(gemm_qkv_kernel,  cudaFuncAttributeMaxDynamicSharedMemorySize, GEMM_SMEM_BYTES);
        cudaFuncSetAttribute(attn_scores_softmax, cudaFuncAttributeMaxDynamicSharedMemorySize, ATT_SMEM_BYTES);
        attr_done = true;
    }

    float* ws = nullptr;
    cudaGetSymbolAddress((void**)&ws, g_ws);
    __half* hws = nullptr;
    cudaGetSymbolAddress((void**)&hws, g_hws);

    float* x     = ws;
    float* x1    = x  + (size_t)Tq * Dq;
    float* tmp32 = x1 + (size_t)Tq * Dq;
    float* bpad  = tmp32 + (size_t)Tq * Dq;

    __half* xH   = hws;
    __half* x1H  = xH  + (size_t)Tq * Dq;
    __half* qH   = x1H + (size_t)Tq * Dq;
    __half* kH   = qH  + (size_t)Tq * Dq;
    __half* vH   = kH  + (size_t)Tq * Dq;
    __half* tbH  = vH  + (size_t)Tq * Dq;
    __half* hbH  = tbH + (size_t)Tq * Dq;
    __half* wpadH = hbH + (size_t)Tq * Fq;
    __half* hWq  = wpadH + (size_t)Dq * Npad;
    __half* hWk  = hWq + LDD;
    __half* hWv  = hWk + LDD;
    __half* hWo  = hWv + LDD;
    __half* hF1  = hWo + LDD;
    __half* hF2  = hF1 + LDF;

    float* logits = (float*)d_out;                       // [B*S, V]
    float* attn   = logits + (size_t)Tq * Vq;            // [L, B*H, S, S]

    // ---- pre-round weights to fp16 + pad vocab ----
    {
        size_t n4dd = LDD / 4;
        unsigned gdd = (unsigned)((n4dd + 255) / 256);
        cvt_half_kernel<<<gdd, 256>>>(Wq, hWq, n4dd);
        cvt_half_kernel<<<gdd, 256>>>(Wk, hWk, n4dd);
        cvt_half_kernel<<<gdd, 256>>>(Wv, hWv, n4dd);
        cvt_half_kernel<<<gdd, 256>>>(Wo, hWo, n4dd);
        size_t n4df = LDF / 4;
        unsigned gdf = (unsigned)((n4df + 255) / 256);
        cvt_half_kernel<<<gdf, 256>>>(f1w, hF1, n4df);
        cvt_half_kernel<<<gdf, 256>>>(f2w, hF2, n4df);
        size_t n4v = ((size_t)Dq * Npad) / 4;
        pad_vocab_kernel<<<(unsigned)((n4v + 255) / 256), 256>>>(outw, wpadH);
        pad_bias_kernel<<<(Npad + 255) / 256, 256>>>(outb, bpad);
    }

    embed_ln_kernel<<<Tq, 256>>>(ids, wemb, pemb, semb, elng, elnb, x, xH);

    for (int l = 0; l < Lq; l++) {
        float* slab = attn + (size_t)l * Bq * Hq * Sq * Sq;
        dim3 gDD(Dq / 128, Tq / 128);  // (6,16)

        gemm_qkv_kernel<<<dim3(Dq / 128, Tq / 128, 3), 256, GEMM_SMEM_BYTES>>>(
            xH, hWq + (size_t)l * Dq * Dq, hWk + (size_t)l * Dq * Dq,
            hWv + (size_t)l * Dq * Dq, qH);

        attn_scores_softmax<<<dim3(Sq / 32, Bq * Hq), 256, ATT_SMEM_BYTES>>>(
            qH, kH, mask, slab);
        attn_av_h<<<dim3(1, Sq / 64, Bq * Hq), 256>>>(slab, vH, tbH);

        gemm_h_kernel<0><<<gDD, 256, GEMM_SMEM_BYTES>>>(
            tbH, hWo + (size_t)l * Dq * Dq, nullptr, tmp32, Dq, Dq, Dq);
        add_ln_kernel<<<Tq, 256>>>(x, tmp32, l1g + (size_t)l * Dq, l1b + (size_t)l * Dq, x1, x1H);

        gemm_h_kernel<2><<<dim3(Fq / 128, Tq / 128), 256, GEMM_SMEM_BYTES>>>(
            x1H, hF1 + (size_t)l * Dq * Fq, f1b + (size_t)l * Fq, hbH, Fq, Dq, Fq);
        gemm_h_kernel<1><<<dim3(Dq / 128, Tq / 128), 256, GEMM_SMEM_BYTES>>>(
            hbH, hF2 + (size_t)l * Fq * Dq, f2b + (size_t)l * Dq, tmp32, Dq, Fq, Dq);
        add_ln_kernel<<<Tq, 256>>>(x1, tmp32, l2g + (size_t)l * Dq, l2b + (size_t)l * Dq, x, xH);
    }

    gemm_h_kernel<1><<<dim3(Npad / 128, Tq / 128), 256, GEMM_SMEM_BYTES>>>(
        xH, wpadH, bpad, logits, Vq, Dq, Npad);
}

// round 14
// speedup vs baseline: 3.3091x; 1.0951x over previous
#include <cuda_runtime.h>
#include <mma.h>
#include <math.h>
#include <cstdint>
#include <cuda_fp16.h>

using namespace nvcuda;

// BERT-base forward: B=4, S=512, L=12, D=768, H=12, F=3072, V=30522
#define Bq 4
#define Sq 512
#define Lq 12
#define Dq 768
#define Hq 12
#define Fq 3072
#define Vq 30522
#define HDq 64
#define Tq 2048    // B*S tokens
#define Npad 30592 // 239*128, padded vocab width

#define LDD ((size_t)Lq * Dq * Dq)
#define LDF ((size_t)Lq * Dq * Fq)

// fp32 workspace: x, x1 [T,D]; tmp32 [2][T,D]; bpad [Npad]
__device__ float g_ws[4 * (size_t)Tq * Dq + Npad];
// fp16 workspace: xH,x1H,qH,kH,vH,tbH [T,D]; hbH [T,F]; wpadH [D,Npad];
// hWq,hWk,hWv,hWo [L,D,D]; hF1 [L,D,F]; hF2 [L,F,D]
__device__ __half g_hws[6 * (size_t)Tq * Dq + (size_t)Tq * Fq
                        + (size_t)Dq * Npad + 4 * LDD + 2 * LDF];

__device__ __forceinline__ __half H16(float x) { return __float2half_rn(x); }

__device__ __forceinline__ void cp16(uint32_t dst, const void* src) {
    asm volatile("cp.async.cg.shared.global [%0], [%1], 16;" :: "r"(dst), "l"(src));
}
__device__ __forceinline__ void cp_commit() {
    asm volatile("cp.async.commit_group;");
}
template <int N>
__device__ __forceinline__ void cp_wait() {
    asm volatile("cp.async.wait_group %0;" :: "n"(N));
}
__device__ __forceinline__ uint32_t smem_u32(const void* p) {
    return (uint32_t)__cvta_generic_to_shared(p);
}

// ---------------------------------------------------------------------------
// Block-wide sum of (a,b) pairs, 256 threads
// ---------------------------------------------------------------------------
__device__ __forceinline__ float2 blockReduce2(float a, float b) {
#pragma unroll
    for (int o = 16; o > 0; o >>= 1) {
        a += __shfl_down_sync(0xffffffffu, a, o);
        b += __shfl_down_sync(0xffffffffu, b, o);
    }
    __shared__ float2 sh[8];
    int lane = threadIdx.x & 31, wid = threadIdx.x >> 5;
    if (lane == 0) sh[wid] = make_float2(a, b);
    __syncthreads();
    if (wid == 0) {
        float2 v = (lane < 8) ? sh[lane] : make_float2(0.f, 0.f);
#pragma unroll
        for (int o = 4; o > 0; o >>= 1) {
            v.x += __shfl_down_sync(0xffffffffu, v.x, o);
            v.y += __shfl_down_sync(0xffffffffu, v.y, o);
        }
        if (lane == 0) sh[0] = v;
    }
    __syncthreads();
    return sh[0];
}

// ---------------------------------------------------------------------------
// Embedding + LayerNorm: fp32 out + fp16-rounded copy
// ---------------------------------------------------------------------------
__global__ void embed_ln_kernel(const int* __restrict__ ids,
                                const float* __restrict__ wemb,
                                const float* __restrict__ pemb,
                                const float* __restrict__ semb,
                                const float* __restrict__ g,
                                const float* __restrict__ bta,
                                float* __restrict__ x,
                                __half* __restrict__ xH) {
    int t = blockIdx.x;
    int s = t & (Sq - 1);
    int id = ids[t];
    float v[3];
    float sum = 0.f, sq = 0.f;
#pragma unroll
    for (int i = 0; i < 3; i++) {
        int d = threadIdx.x + i * 256;
        float val = wemb[(size_t)id * Dq + d] + pemb[(size_t)s * Dq + d] + semb[d];
        v[i] = val;
        sum += val;
        sq += val * val;
    }
    float2 r = blockReduce2(sum, sq);
    float mu = r.x * (1.0f / Dq);
    float var = r.y * (1.0f / Dq) - mu * mu;
    float rstd = rsqrtf(var + 1e-5f);
#pragma unroll
    for (int i = 0; i < 3; i++) {
        int d = threadIdx.x + i * 256;
        float o = (v[i] - mu) * rstd * g[d] + bta[d];
        x[(size_t)t * Dq + d] = o;
        xH[(size_t)t * Dq + d] = H16(o);
    }
}

// ---------------------------------------------------------------------------
// out = LayerNorm(a + b0 + b1 + bias?): fp32 out + fp16 copy (split-K merge)
// ---------------------------------------------------------------------------
__global__ void add_ln3_kernel(const float* __restrict__ a,
                               const float* __restrict__ b0,
                               const float* __restrict__ b1,
                               const float* __restrict__ bias,
                               const float* __restrict__ g,
                               const float* __restrict__ bta,
                               float* __restrict__ out,
                               __half* __restrict__ outH) {
    int t = blockIdx.x;
    float v[3];
    float sum = 0.f, sq = 0.f;
#pragma unroll
    for (int i = 0; i < 3; i++) {
        int d = threadIdx.x + i * 256;
        size_t idx = (size_t)t * Dq + d;
        float val = a[idx] + b0[idx] + b1[idx];
        if (bias) val += bias[d];
        v[i] = val;
        sum += val;
        sq += val * val;
    }
    float2 r = blockReduce2(sum, sq);
    float mu = r.x * (1.0f / Dq);
    float var = r.y * (1.0f / Dq) - mu * mu;
    float rstd = rsqrtf(var + 1e-5f);
#pragma unroll
    for (int i = 0; i < 3; i++) {
        int d = threadIdx.x + i * 256;
        float o = (v[i] - mu) * rstd * g[d] + bta[d];
        out[(size_t)t * Dq + d] = o;
        outH[(size_t)t * Dq + d] = H16(o);
    }
}

// ---------------------------------------------------------------------------
// Elementwise fp32 -> fp16 (RNE), n multiple of 4
// ---------------------------------------------------------------------------
__global__ void cvt_half_kernel(const float* __restrict__ in,
                                __half* __restrict__ out, size_t n4) {
    size_t i = (size_t)blockIdx.x * 256 + threadIdx.x;
    if (i >= n4) return;
    float4 v = ((const float4*)in)[i];
    ((__half2*)out)[i * 2 + 0] = __floats2half2_rn(v.x, v.y);
    ((__half2*)out)[i * 2 + 1] = __floats2half2_rn(v.z, v.w);
}

__global__ void pad_vocab_kernel(const float* __restrict__ w,
                                 __half* __restrict__ wp) {
    size_t gid = (size_t)blockIdx.x * 256 + threadIdx.x;
    size_t i4 = gid * 4;
    if (i4 >= (size_t)Dq * Npad) return;
    int k = (int)(i4 / Npad);
    int c = (int)(i4 % Npad);
    float a = (c + 0 < Vq) ? w[(size_t)k * Vq + c + 0] : 0.f;
    float b = (c + 1 < Vq) ? w[(size_t)k * Vq + c + 1] : 0.f;
    float d = (c + 2 < Vq) ? w[(size_t)k * Vq + c + 2] : 0.f;
    float e = (c + 3 < Vq) ? w[(size_t)k * Vq + c + 3] : 0.f;
    ((__half2*)wp)[gid * 2 + 0] = __floats2half2_rn(a, b);
    ((__half2*)wp)[gid * 2 + 1] = __floats2half2_rn(d, e);
}

__global__ void pad_bias_kernel(const float* __restrict__ b,
                                float* __restrict__ bp) {
    int c = blockIdx.x * 256 + threadIdx.x;
    if (c < Npad) bp[c] = (c < Vq) ? b[c] : 0.f;
}

// ---------------------------------------------------------------------------
// FP16 WMMA GEMM, cp.async 4-stage: C[M,N] = A[M, kOff:kOff+Klen] @ B slice.
// 128x128 tile, BK=32, 8 warps (4 M x 2 N), warp tile 32x64, fp32 accum.
// MODE: 0 = float out, plain (direct frag store)
//       1 = float out, +bias (staged)
//       2 = half out, +bias + exact GELU (staged)
//       3 = half out, plain (staged)
// ---------------------------------------------------------------------------
#define AS_LD 40
#define BS_LD 136
#define STAGE_HALFS (128 * AS_LD + 32 * BS_LD)        // 9472
#define GEMM_SMEM_BYTES (4 * STAGE_HALFS * 2)         // 75776

template <int MODE>
__device__ __forceinline__ void gemm_body(const __half* __restrict__ A,
                                          const __half* __restrict__ Bt,
                                          const float* __restrict__ bias,
                                          void* __restrict__ Cv,
                                          int N, int Klen, int ldA, int ldB,
                                          int kOff) {
    extern __shared__ char smraw[];
    __half* smh = (__half*)smraw;
    float* smf = (float*)smraw;
    uint32_t smb = smem_u32(smraw);

    int tid = threadIdx.x;
    int row0 = blockIdx.y * 128, col0 = blockIdx.x * 128;
    int warp = tid >> 5, lane = tid & 31;
    int wm = warp & 3, wn = warp >> 2;

    wmma::fragment<wmma::accumulator, 16, 16, 16, float> acc[2][4];
#pragma unroll
    for (int i = 0; i < 2; i++)
#pragma unroll
        for (int j = 0; j < 4; j++)
            wmma::fill_fragment(acc[i][j], 0.0f);

    auto issue = [&](int i) {
        uint32_t sb = smb + (uint32_t)((i & 3) * STAGE_HALFS) * 2;
        uint32_t bb = sb + 128 * AS_LD * 2;
        int k0 = kOff + (i << 5);
#pragma unroll
        for (int it = 0; it < 2; it++) {
            int idx = tid + it * 256;
            int r = idx >> 2, c = idx & 3;
            cp16(sb + (uint32_t)((r * AS_LD + c * 8) * 2),
                 A + (size_t)(row0 + r) * ldA + k0 + c * 8);
        }
#pragma unroll
        for (int it = 0; it < 2; it++) {
            int idx = tid + it * 256;
            int r = idx >> 4, c = idx & 15;
            cp16(bb + (uint32_t)((r * BS_LD + c * 8) * 2),
                 Bt + (size_t)(k0 + r) * ldB + col0 + c * 8);
        }
        cp_commit();
    };

    int niter = Klen >> 5;
    issue(0);
    if (niter > 1) issue(1);
    if (niter > 2) issue(2);

    for (int i = 0; i < niter; i++) {
        if (i + 3 < niter) {
            issue(i + 3);
            cp_wait<3>();
        } else if (i + 2 < niter) {
            cp_wait<2>();
        } else if (i + 1 < niter) {
            cp_wait<1>();
        } else {
            cp_wait<0>();
        }
        __syncthreads();

        const __half* as = smh + (i & 3) * STAGE_HALFS;
        const __half* bs = as + 128 * AS_LD;
#pragma unroll
        for (int kk = 0; kk < 2; kk++) {
            wmma::fragment<wmma::matrix_a, 16, 16, 16, __half, wmma::row_major> af[2];
            wmma::fragment<wmma::matrix_b, 16, 16, 16, __half, wmma::row_major> bf[4];
#pragma unroll
            for (int ii = 0; ii < 2; ii++)
                wmma::load_matrix_sync(af[ii], as + (wm * 32 + ii * 16) * AS_LD + kk * 16, AS_LD);
#pragma unroll
            for (int j = 0; j < 4; j++)
                wmma::load_matrix_sync(bf[j], bs + (kk * 16) * BS_LD + wn * 64 + j * 16, BS_LD);
#pragma unroll
            for (int ii = 0; ii < 2; ii++)
#pragma unroll
                for (int j = 0; j < 4; j++)
                    wmma::mma_sync(acc[ii][j], af[ii], bf[j], acc[ii][j]);
        }
        __syncthreads();
    }

    if (MODE == 0) {
        float* C = (float*)Cv;
#pragma unroll
        for (int i = 0; i < 2; i++)
#pragma unroll
            for (int j = 0; j < 4; j++) {
                float* dst = C + (size_t)(row0 + wm * 32 + i * 16) * N
                               + col0 + wn * 64 + j * 16;
                wmma::store_matrix_sync(dst, acc[i][j], N, wmma::mem_row_major);
            }
    } else {
        float* Cs = smf + warp * 320;
        int rr = lane >> 1, cc = (lane & 1) * 8;
#pragma unroll
        for (int i = 0; i < 2; i++) {
#pragma unroll
            for (int j = 0; j < 4; j++) {
                wmma::store_matrix_sync(Cs, acc[i][j], 20, wmma::mem_row_major);
                __syncwarp();
                int r = row0 + wm * 32 + i * 16 + rr;
                int c0l = col0 + wn * 64 + j * 16 + cc;
#pragma unroll
                for (int e = 0; e < 8; e++) {
                    int c = c0l + e;
                    if (c < N) {
                        float vv = Cs[rr * 20 + cc + e];
                        if (MODE == 1 || MODE == 2) vv += bias[c];
                        if (MODE == 2)
                            vv = 0.5f * vv * (1.0f + erff(vv * 0.70710678118654752f));
                        if (MODE == 1)
                            ((float*)Cv)[(size_t)r * N + c] = vv;
                        else
                            ((__half*)Cv)[(size_t)r * N + c] = H16(vv);
                    }
                }
                __syncwarp();
            }
        }
    }
}

template <int MODE>
__global__ void __launch_bounds__(256, 2)
gemm_h_kernel(const __half* __restrict__ A, const __half* __restrict__ Bt,
              const float* __restrict__ bias, void* __restrict__ Cv,
              int N, int K, int ldB) {
    gemm_body<MODE>(A, Bt, bias, Cv, N, K, K, ldB, 0);
}

// Split-K=2: blockIdx.z picks K-half; writes fp32 partial slab z.
__global__ void __launch_bounds__(256, 2)
gemm_h_splitk(const __half* __restrict__ A, const __half* __restrict__ Bt,
              float* __restrict__ C, int N, int K, int ldB) {
    int z = blockIdx.z;
    int kh = K >> 1;
    gemm_body<0>(A, Bt, nullptr, (void*)(C + (size_t)z * Tq * Dq),
                 N, kh, K, ldB, z * kh);
}

// Batched QKV: blockIdx.z selects weight + output slab; outputs half
__global__ void __launch_bounds__(256, 2)
gemm_qkv_kernel(const __half* __restrict__ A, const __half* __restrict__ w0,
                const __half* __restrict__ w1, const __half* __restrict__ w2,
                __half* __restrict__ c0) {
    const __half* Bm = (blockIdx.z == 0) ? w0 : (blockIdx.z == 1) ? w1 : w2;
    __half* C = c0 + (size_t)blockIdx.z * Tq * Dq;
    gemm_body<3>(A, Bm, nullptr, (void*)C, Dq, Dq, Dq, Dq, 0);
}

// ---------------------------------------------------------------------------
// Fully fused attention: scores (fp16 MMA) -> softmax (fp32) -> write probs
// -> P·V (fp16 MMA) -> write O (half). grid (S/32, B*H), 256 threads.
// Smem: Qs[32][72]h | Ks[64][72]h (reused for V) | Sc[32][520]f | Ph[32][520]h
// ---------------------------------------------------------------------------
#define ATTQ_HALFS (32 * 72)
#define ATTK_HALFS (64 * 72)
#define SC_LD 520
#define PH_OFF_BYTES ((ATTQ_HALFS + ATTK_HALFS) * 2 + 32 * SC_LD * 4)
#define ATT_SMEM_BYTES (PH_OFF_BYTES + 32 * SC_LD * 2)

__global__ void __launch_bounds__(256)
attn_fused(const __half* __restrict__ q, const __half* __restrict__ k,
           const __half* __restrict__ v, const int* __restrict__ mask,
           float* __restrict__ probs, __half* __restrict__ o) {
    extern __shared__ char asmraw[];
    __half* Qs = (__half*)asmraw;                                   // [32][72]
    __half* Ks = Qs + ATTQ_HALFS;                                   // [64][72]
    float* Sc = (float*)(asmraw + (ATTQ_HALFS + ATTK_HALFS) * 2);   // [32][520]
    __half* Ph = (__half*)(asmraw + PH_OFF_BYTES);                  // [32][520]

    int bh = blockIdx.y;
    int b = bh / Hq, h = bh % Hq;
    int q0 = blockIdx.x * 32;
    int tid = threadIdx.x;
    int warp = tid >> 5, lane = tid & 31;

    // ---- Phase 1: scores = Q K^T ----
    {
        int r = tid >> 3, c = tid & 7;
        *(uint4*)(Qs + r * 72 + c * 8) =
            *(const uint4*)(q + (size_t)(b * Sq + q0 + r) * Dq + h * HDq + c * 8);
    }
    int wm2 = warp & 1, wn4 = warp >> 1;   // 2 m x 4 n
    for (int kt = 0; kt < 8; kt++) {
        __syncthreads();
#pragma unroll
        for (int i = 0; i < 2; i++) {
            int idx = tid + i * 256;
            int r = idx >> 3, c = idx & 7;
            *(uint4*)(Ks + r * 72 + c * 8) =
                *(const uint4*)(k + (size_t)(b * Sq + kt * 64 + r) * Dq + h * HDq + c * 8);
        }
        __syncthreads();

        wmma::fragment<wmma::accumulator, 16, 16, 16, float> acc;
        wmma::fill_fragment(acc, 0.0f);
#pragma unroll
        for (int kk = 0; kk < 4; kk++) {
            wmma::fragment<wmma::matrix_a, 16, 16, 16, __half, wmma::row_major> af;
            wmma::fragment<wmma::matrix_b, 16, 16, 16, __half, wmma::col_major> bf;
            wmma::load_matrix_sync(af, Qs + (wm2 * 16) * 72 + kk * 16, 72);
            wmma::load_matrix_sync(bf, Ks + (wn4 * 16) * 72 + kk * 16, 72);
            wmma::mma_sync(acc, af, bf, acc);
        }
        wmma::store_matrix_sync(Sc + (wm2 * 16) * SC_LD + kt * 64 + wn4 * 16,
                                acc, SC_LD, wmma::mem_row_major);
    }
    __syncthreads();

    // ---- Phase 2: softmax; write probs (fp32) + keep half copy in Ph ----
    const float scale = 0.03608439182435161f;  // 1/sqrt(D=768)
#pragma unroll
    for (int i = 0; i < 4; i++) {
        int r = warp * 4 + i;
        float vv[16];
        float m = -INFINITY;
#pragma unroll
        for (int j = 0; j < 16; j++) {
            int col = lane + j * 32;
            float f = Sc[r * SC_LD + col] * scale;
            if (mask[b * Sq + col] == 0) f = -INFINITY;
            vv[j] = f;
            m = fmaxf(m, f);
        }
#pragma unroll
        for (int oo = 16; oo > 0; oo >>= 1) m = fmaxf(m, __shfl_xor_sync(0xffffffffu, m, oo));
        float s = 0.f;
#pragma unroll
        for (int j = 0; j < 16; j++) {
            vv[j] = __expf(vv[j] - m);
            s += vv[j];
        }
#pragma unroll
        for (int oo = 16; oo > 0; oo >>= 1) s += __shfl_xor_sync(0xffffffffu, s, oo);
        float inv = 1.0f / s;
        float* dst = probs + ((size_t)bh * Sq + q0 + r) * Sq;
#pragma unroll
        for (int j = 0; j < 16; j++) {
            float pv = vv[j] * inv;
            dst[lane + j * 32] = pv;
            Ph[r * SC_LD + lane + j * 32] = H16(pv);
        }
    }
    __syncthreads();

    // ---- Phase 3: O = P V (accumulate across 8 V-tiles of 64 keys) ----
    // 8 warps -> 2x4 grid of 16x16 output frags covering [32, 64]
    wmma::fragment<wmma::accumulator, 16, 16, 16, float> oacc;
    wmma::fill_fragment(oacc, 0.0f);
    for (int kt = 0; kt < 8; kt++) {
        __syncthreads();
#pragma unroll
        for (int i = 0; i < 2; i++) {
            int idx = tid + i * 256;
            int r = idx >> 3, c = idx & 7;
            *(uint4*)(Ks + r * 72 + c * 8) =
                *(const uint4*)(v + (size_t)(b * Sq + kt * 64 + r) * Dq + h * HDq + c * 8);
        }
        __syncthreads();
#pragma unroll
        for (int kk = 0; kk < 4; kk++) {
            wmma::fragment<wmma::matrix_a, 16, 16, 16, __half, wmma::row_major> af;
            wmma::fragment<wmma::matrix_b, 16, 16, 16, __half, wmma::row_major> bf;
            wmma::load_matrix_sync(af, Ph + (wm2 * 16) * SC_LD + kt * 64 + kk * 16, SC_LD);
            wmma::load_matrix_sync(bf, Ks + (kk * 16) * 72 + wn4 * 16, 72);
            wmma::mma_sync(oacc, af, bf, oacc);
        }
    }
    __syncthreads();

    // stage via Sc (free now), convert to half, write O
    float* Cs = Sc + warp * 320;  // [16][20]
    wmma::store_matrix_sync(Cs, oacc, 20, wmma::mem_row_major);
    __syncwarp();
    int rr = lane >> 1, cc = (lane & 1) * 8;
    int qr = q0 + wm2 * 16 + rr;
    int dc = h * HDq + wn4 * 16 + cc;
    __half* dst = o + (size_t)(b * Sq + qr) * Dq + dc;
#pragma unroll
    for (int e = 0; e < 8; e++) dst[e] = H16(Cs[rr * 20 + cc + e]);
}

// ---------------------------------------------------------------------------
// Host orchestration (graph-capturable: kernel launches only)
// ---------------------------------------------------------------------------
extern "C" void kernel_launch(void* const* d_in, const int* in_sizes, int n_in,
                              void* d_out, int out_size) {
    const int*   ids  = (const int*)d_in[0];
    const int*   mask = (const int*)d_in[1];
    const float* wemb = (const float*)d_in[2];
    const float* pemb = (const float*)d_in[3];
    const float* semb = (const float*)d_in[4];
    const float* elng = (const float*)d_in[5];
    const float* elnb = (const float*)d_in[6];
    const float* Wq   = (const float*)d_in[7];
    const float* Wk   = (const float*)d_in[8];
    const float* Wv   = (const float*)d_in[9];
    const float* Wo   = (const float*)d_in[10];
    const float* f1w  = (const float*)d_in[11];
    const float* f1b  = (const float*)d_in[12];
    const float* f2w  = (const float*)d_in[13];
    const float* f2b  = (const float*)d_in[14];
    const float* l1g  = (const float*)d_in[15];
    const float* l1b  = (const float*)d_in[16];
    const float* l2g  = (const float*)d_in[17];
    const float* l2b  = (const float*)d_in[18];
    const float* outw = (const float*)d_in[19];
    const float* outb = (const float*)d_in[20];

    static bool attr_done = false;
    if (!attr_done) {
        cudaFuncSetAttribute(gemm_h_kernel<0>, cudaFuncAttributeMaxDynamicSharedMemorySize, GEMM_SMEM_BYTES);
        cudaFuncSetAttribute(gemm_h_kernel<1>, cudaFuncAttributeMaxDynamicSharedMemorySize, GEMM_SMEM_BYTES);
        cudaFuncSetAttribute(gemm_h_kernel<2>, cudaFuncAttributeMaxDynamicSharedMemorySize, GEMM_SMEM_BYTES);
        cudaFuncSetAttribute(gemm_h_kernel<3>, cudaFuncAttributeMaxDynamicSharedMemorySize, GEMM_SMEM_BYTES);
        cudaFuncSetAttribute(gemm_h_splitk,    cudaFuncAttributeMaxDynamicSharedMemorySize, GEMM_SMEM_BYTES);
        cudaFuncSetAttribute(gemm_qkv_kernel,  cudaFuncAttributeMaxDynamicSharedMemorySize, GEMM_SMEM_BYTES);
        cudaFuncSetAttribute(attn_fused,       cudaFuncAttributeMaxDynamicSharedMemorySize, ATT_SMEM_BYTES);
        attr_done = true;
    }

    float* ws = nullptr;
    cudaGetSymbolAddress((void**)&ws, g_ws);
    __half* hws = nullptr;
    cudaGetSymbolAddress((void**)&hws, g_hws);

    float* x     = ws;
    float* x1    = x  + (size_t)Tq * Dq;
    float* tmp32 = x1 + (size_t)Tq * Dq;            // 2 slabs
    float* bpad  = tmp32 + 2 * (size_t)Tq * Dq;

    __half* xH   = hws;
    __half* x1H  = xH  + (size_t)Tq * Dq;
    __half* qH   = x1H + (size_t)Tq * Dq;
    __half* kH   = qH  + (size_t)Tq * Dq;
    __half* vH   = kH  + (size_t)Tq * Dq;
    __half* tbH  = vH  + (size_t)Tq * Dq;
    __half* hbH  = tbH + (size_t)Tq * Dq;
    __half* wpadH = hbH + (size_t)Tq * Fq;
    __half* hWq  = wpadH + (size_t)Dq * Npad;
    __half* hWk  = hWq + LDD;
    __half* hWv  = hWk + LDD;
    __half* hWo  = hWv + LDD;
    __half* hF1  = hWo + LDD;
    __half* hF2  = hF1 + LDF;

    float* logits = (float*)d_out;                       // [B*S, V]
    float* attn   = logits + (size_t)Tq * Vq;            // [L, B*H, S, S]

    // ---- pre-round weights to fp16 + pad vocab ----
    {
        size_t n4dd = LDD / 4;
        unsigned gdd = (unsigned)((n4dd + 255) / 256);
        cvt_half_kernel<<<gdd, 256>>>(Wq, hWq, n4dd);
        cvt_half_kernel<<<gdd, 256>>>(Wk, hWk, n4dd);
        cvt_half_kernel<<<gdd, 256>>>(Wv, hWv, n4dd);
        cvt_half_kernel<<<gdd, 256>>>(Wo, hWo, n4dd);
        size_t n4df = LDF / 4;
        unsigned gdf = (unsigned)((n4df + 255) / 256);
        cvt_half_kernel<<<gdf, 256>>>(f1w, hF1, n4df);
        cvt_half_kernel<<<gdf, 256>>>(f2w, hF2, n4df);
        size_t n4v = ((size_t)Dq * Npad) / 4;
        pad_vocab_kernel<<<(unsigned)((n4v + 255) / 256), 256>>>(outw, wpadH);
        pad_bias_kernel<<<(Npad + 255) / 256, 256>>>(outb, bpad);
    }

    embed_ln_kernel<<<Tq, 256>>>(ids, wemb, pemb, semb, elng, elnb, x, xH);

    for (int l = 0; l < Lq; l++) {
        float* slab = attn + (size_t)l * Bq * Hq * Sq * Sq;
        dim3 gDD(Dq / 128, Tq / 128);  // (6,16)

        gemm_qkv_kernel<<<dim3(Dq / 128, Tq / 128, 3), 256, GEMM_SMEM_BYTES>>>(
            xH, hWq + (size_t)l * Dq * Dq, hWk + (size_t)l * Dq * Dq,
            hWv + (size_t)l * Dq * Dq, qH);

        attn_fused<<<dim3(Sq / 32, Bq * Hq), 256, ATT_SMEM_BYTES>>>(
            qH, kH, vH, mask, slab, tbH);

        gemm_h_splitk<<<dim3(Dq / 128, Tq / 128, 2), 256, GEMM_SMEM_BYTES>>>(
            tbH, hWo + (size_t)l * Dq * Dq, tmp32, Dq, Dq, Dq);
        add_ln3_kernel<<<Tq, 256>>>(x, tmp32, tmp32 + (size_t)Tq * Dq, nullptr,
                                    l1g + (size_t)l * Dq, l1b + (size_t)l * Dq, x1, x1H);

        gemm_h_kernel<2><<<dim3(Fq / 128, Tq / 128), 256, GEMM_SMEM_BYTES>>>(
            x1H, hF1 + (size_t)l * Dq * Fq, f1b + (size_t)l * Fq, hbH, Fq, Dq, Fq);
        gemm_h_splitk<<<dim3(Dq / 128, Tq / 128, 2), 256, GEMM_SMEM_BYTES>>>(
            hbH, hF2 + (size_t)l * Fq * Dq, tmp32, Dq, Fq, Dq);
        add_ln3_kernel<<<Tq, 256>>>(x1, tmp32, tmp32 + (size_t)Tq * Dq,
                                    f2b + (size_t)l * Dq,
                                    l2g + (size_t)l * Dq, l2b + (size_t)l * Dq, x, xH);
    }

    gemm_h_kernel<1><<<dim3(Npad / 128, Tq / 128), 256, GEMM_SMEM_BYTES>>>(
        xH, wpadH, bpad, logits, Vq, Dq, Npad);
}